// round 12
// baseline (speedup 1.0000x reference)
#include <cuda_runtime.h>
#include <cuda_bf16.h>
#include <cuda_fp16.h>
#include <math.h>
#include <float.h>
#include <stdint.h>

#define TT 2048
#define HIDN 4096
#define NHQ 32
#define NKVH 8
#define HDIM 128
#define QKVO 6144
#define SCALE_QK 0.08838834764831845f

// ---------------- device scratch (static; no cudaMalloc) ----------------
static __device__ __nv_bfloat16 g_A[(size_t)TT * HIDN];
static __device__ float         g_asum[TT];
static __device__ __nv_bfloat16 g_Wqkv[(size_t)QKVO * HIDN];
static __device__ __nv_bfloat16 g_Wo[(size_t)HIDN * HIDN];
static __device__ float         g_qkv[(size_t)TT * QKVO];
static __device__ float         g_attn[(size_t)TT * HIDN];
static __device__ __nv_bfloat16 g_q2[(size_t)TT * HIDN];
static __device__ float         g_s2[TT];
static __device__ float         g_sum2[TT];
static __device__ float         g_cos[TT * 64];
static __device__ float         g_sin[TT * 64];

__device__ __forceinline__ uint32_t s2u(const void* p) { return (uint32_t)__cvta_generic_to_shared(p); }

// ---------------- RoPE table (fp64 inner) ----------------
__global__ void k_rope_tab(const int* __restrict__ pos) {
    int t = blockIdx.x, i = threadIdx.x;               // i: 0..63
    float ef = (float)(2 * i) / 128.0f;
    float invf = (float)(1.0 / pow(10000.0, (double)ef));
    float fr = (float)pos[t] * invf;                   // fp32 mul = reference rounding
    g_cos[t * 64 + i] = (float)cos((double)fr);
    g_sin[t * 64 + i] = (float)sin((double)fr);
}

// ---------------- activation prep ----------------
__global__ void k_prep_a(const int* __restrict__ qa) {
    int t = blockIdx.x, tid = threadIdx.x;
    const int* row = qa + (size_t)t * HIDN;
    __nv_bfloat16* arow = g_A + (size_t)t * HIDN;
    int s = 0;
    for (int c = tid; c < HIDN; c += 256) { int v = row[c]; s += v; arow[c] = __float2bfloat16((float)v); }
    __shared__ int red[256];
    red[tid] = s; __syncthreads();
    for (int k = 128; k > 0; k >>= 1) { if (tid < k) red[tid] += red[tid + k]; __syncthreads(); }
    if (tid == 0) g_asum[t] = (float)red[0];
}

__global__ void k_conv_w(const int* __restrict__ w, __nv_bfloat16* __restrict__ o, int n) {
    int i = blockIdx.x * blockDim.x + threadIdx.x;
    int stride = gridDim.x * blockDim.x;
    for (int v = i; v < n / 4; v += stride) {
        int4 x = ((const int4*)w)[v];
        __nv_bfloat162 p0 = {__float2bfloat16((float)x.x), __float2bfloat16((float)x.y)};
        __nv_bfloat162 p1 = {__float2bfloat16((float)x.z), __float2bfloat16((float)x.w)};
        ((__nv_bfloat162*)o)[2 * v] = p0;
        ((__nv_bfloat162*)o)[2 * v + 1] = p1;
    }
}

// ==================================================================
// bf16 HMMA GEMM v4: CTA 256x128, 512 threads, warp tile 64x32
// (4x4 warps), 3-stage cp.async pipeline, ldmatrix fragments,
// fused W4A8 epilogue. Bit-exact integer arithmetic.
// ==================================================================
#define GST 40
#define ASTG (256 * GST)
#define BSTG (128 * GST)
#define GEMM_SMEM (3 * (ASTG + BSTG) * 2)

__device__ __forceinline__ void ldsm4(uint32_t& r0, uint32_t& r1, uint32_t& r2, uint32_t& r3, uint32_t a) {
    asm volatile("ldmatrix.sync.aligned.m8n8.x4.shared.b16 {%0,%1,%2,%3},[%4];\n"
                 : "=r"(r0), "=r"(r1), "=r"(r2), "=r"(r3) : "r"(a));
}
__device__ __forceinline__ void mmabf(float* c, const uint32_t* a, uint32_t b0, uint32_t b1) {
    asm volatile("mma.sync.aligned.m16n8k16.row.col.f32.bf16.bf16.f32 "
                 "{%0,%1,%2,%3},{%4,%5,%6,%7},{%8,%9},{%0,%1,%2,%3};\n"
                 : "+f"(c[0]), "+f"(c[1]), "+f"(c[2]), "+f"(c[3])
                 : "r"(a[0]), "r"(a[1]), "r"(a[2]), "r"(a[3]), "r"(b0), "r"(b1));
}
#define CP16(dst, src) asm volatile("cp.async.cg.shared.global [%0], [%1], 16;\n" :: "r"(dst), "l"(src))
#define CPCOMMIT()     asm volatile("cp.async.commit_group;\n")
#define CPWAIT1()      asm volatile("cp.async.wait_group 1;\n" ::: "memory")

__global__ __launch_bounds__(512, 1) void k_gemm(
    const __nv_bfloat16* __restrict__ A, const __nv_bfloat16* __restrict__ B,
    float* __restrict__ C, int M, int N, int K,
    const float* __restrict__ rs, const float* __restrict__ rsum,
    const float* __restrict__ cs, const float* __restrict__ cz)
{
    extern __shared__ __nv_bfloat16 gsm[];
    __nv_bfloat16* Ash = gsm;
    __nv_bfloat16* Bsh = gsm + 3 * ASTG;

    const int tid = threadIdx.x;
    const int warp = tid >> 5, lane = tid & 31;
    const int wm = warp >> 2, wn = warp & 3;            // 4x4 warps, warp tile 64x32
    const int g = lane >> 2, tq = lane & 3;
    const int sel = lane >> 3, l7 = lane & 7;
    const int bm0 = blockIdx.y * 256, bn0 = blockIdx.x * 128;

    const int r0 = tid >> 2, c0 = (tid & 3) * 8;        // loader lanes: rows r0 (+128 for A)
    const __nv_bfloat16* Abase = A + (size_t)(bm0 + r0) * K + c0;
    const __nv_bfloat16* Bbase = B + (size_t)(bn0 + r0) * K + c0;
    const size_t rowK128 = (size_t)128 * K;

    uint32_t sA = s2u(Ash), sB = s2u(Bsh);
    uint32_t dA = sA + (r0 * GST + c0) * 2;
    uint32_t dB = sB + (r0 * GST + c0) * 2;

    uint32_t aA = sA + ((wm * 64 + (sel & 1) * 8 + l7) * GST + (sel >> 1) * 8) * 2;
    uint32_t aB = sB + ((wn * 32 + (sel >> 1) * 8 + l7) * GST + (sel & 1) * 8) * 2;

    float acc[4][4][4];
#pragma unroll
    for (int i = 0; i < 4; i++)
#pragma unroll
        for (int j = 0; j < 4; j++) { acc[i][j][0]=0.f; acc[i][j][1]=0.f; acc[i][j][2]=0.f; acc[i][j][3]=0.f; }

    const int KT = K >> 5;

    // preload stages 0 and 1
#pragma unroll
    for (int s = 0; s < 2; s++) {
        const __nv_bfloat16* Ak = Abase + s * 32;
        const __nv_bfloat16* Bk = Bbase + s * 32;
        uint32_t oA = dA + s * ASTG * 2, oB = dB + s * BSTG * 2;
        CP16(oA, Ak);  CP16(oA + 128 * GST * 2, Ak + rowK128);
        CP16(oB, Bk);
        CPCOMMIT();
    }
    CPWAIT1();
    __syncthreads();

    for (int kb = 0; kb < KT; kb++) {
        const int st = kb % 3;
        if (kb + 2 < KT) {
            const int ns = (kb + 2) % 3;
            const __nv_bfloat16* Ak = Abase + (kb + 2) * 32;
            const __nv_bfloat16* Bk = Bbase + (kb + 2) * 32;
            uint32_t oA = dA + ns * ASTG * 2, oB = dB + ns * BSTG * 2;
            CP16(oA, Ak);  CP16(oA + 128 * GST * 2, Ak + rowK128);
            CP16(oB, Bk);
            CPCOMMIT();
        }
        const uint32_t stA = aA + st * ASTG * 2;
        const uint32_t stB = aB + st * BSTG * 2;
#pragma unroll
        for (int ks = 0; ks < 2; ks++) {
            uint32_t af[4][4], bf[2][4];
#pragma unroll
            for (int mi = 0; mi < 4; mi++)
                ldsm4(af[mi][0], af[mi][1], af[mi][2], af[mi][3], stA + mi * 16 * GST * 2 + ks * 32);
#pragma unroll
            for (int p = 0; p < 2; p++)
                ldsm4(bf[p][0], bf[p][1], bf[p][2], bf[p][3], stB + p * 16 * GST * 2 + ks * 32);
#pragma unroll
            for (int mi = 0; mi < 4; mi++)
#pragma unroll
                for (int p = 0; p < 2; p++) {
                    mmabf(acc[mi][2 * p],     af[mi], bf[p][0], bf[p][1]);
                    mmabf(acc[mi][2 * p + 1], af[mi], bf[p][2], bf[p][3]);
                }
        }
        if (kb + 1 < KT) {
            CPWAIT1();
            __syncthreads();
        }
    }

    // epilogue: out = (s_a*s_w) * (acc - z_w*a_sum)   (reference op order)
#pragma unroll
    for (int mi = 0; mi < 4; mi++) {
        int rA = bm0 + wm * 64 + mi * 16 + g;
        int rB = rA + 8;
        float rsA = rs[rA], rmA = rsum[rA];
        float rsB = rs[rB], rmB = rsum[rB];
#pragma unroll
        for (int ni = 0; ni < 4; ni++) {
            int col = bn0 + wn * 32 + ni * 8 + 2 * tq;
            float cs0 = cs[col], cs1 = cs[col + 1];
            float cz0 = cz[col], cz1 = cz[col + 1];
            float2 o0, o1;
            o0.x = (rsA * cs0) * (acc[mi][ni][0] - cz0 * rmA);
            o0.y = (rsA * cs1) * (acc[mi][ni][1] - cz1 * rmA);
            o1.x = (rsB * cs0) * (acc[mi][ni][2] - cz0 * rmB);
            o1.y = (rsB * cs1) * (acc[mi][ni][3] - cz1 * rmB);
            *(float2*)&C[(size_t)rA * N + col] = o0;
            *(float2*)&C[(size_t)rB * N + col] = o1;
        }
    }
}

// ======================================================================
// fp16 split-precision flash attention v4: BM=128, BN=64 (the fast R6
// shape), RoPE fused into the Q/K smem loads (reads g_qkv directly).
// ======================================================================
#define FS 136
#define FLASH_SMEM4 ((128 * FS * 2 + 64 * FS * 4) * 2)   // 139264 B

__device__ __forceinline__ void ldsm4t(uint32_t& r0, uint32_t& r1, uint32_t& r2, uint32_t& r3, uint32_t a) {
    asm volatile("ldmatrix.sync.aligned.m8n8.x4.trans.shared.b16 {%0,%1,%2,%3},[%4];\n"
                 : "=r"(r0), "=r"(r1), "=r"(r2), "=r"(r3) : "r"(a));
}
__device__ __forceinline__ void mmaf16(float* c, const uint32_t* a, uint32_t b0, uint32_t b1) {
    asm volatile("mma.sync.aligned.m16n8k16.row.col.f32.f16.f16.f32 "
                 "{%0,%1,%2,%3},{%4,%5,%6,%7},{%8,%9},{%0,%1,%2,%3};\n"
                 : "+f"(c[0]), "+f"(c[1]), "+f"(c[2]), "+f"(c[3])
                 : "r"(a[0]), "r"(a[1]), "r"(a[2]), "r"(a[3]), "r"(b0), "r"(b1));
}
__device__ __forceinline__ uint32_t ph2(__half a, __half b) {
    return (uint32_t)__half_as_ushort(a) | ((uint32_t)__half_as_ushort(b) << 16);
}
__device__ __forceinline__ void split4(float4 v, uint2& hi, uint2& lo) {
    __half a = __float2half_rn(v.x), b = __float2half_rn(v.y);
    __half c = __float2half_rn(v.z), d = __float2half_rn(v.w);
    hi.x = ph2(a, b); hi.y = ph2(c, d);
    lo.x = ph2(__float2half_rn(v.x - __half2float(a)), __float2half_rn(v.y - __half2float(b)));
    lo.y = ph2(__float2half_rn(v.z - __half2float(c)), __float2half_rn(v.w - __half2float(d)));
}
__device__ __forceinline__ void splitp(float x, float y, uint32_t& hi, uint32_t& lo) {
    __half a = __float2half_rn(x), b = __float2half_rn(y);
    hi = ph2(a, b);
    lo = ph2(__float2half_rn(x - __half2float(a)), __float2half_rn(y - __half2float(b)));
}
__device__ __forceinline__ void rope4(float4 x1, float4 x2, float4 c, float4 s, float4& o1, float4& o2) {
    o1.x = x1.x * c.x - x2.x * s.x;  o2.x = x2.x * c.x + x1.x * s.x;
    o1.y = x1.y * c.y - x2.y * s.y;  o2.y = x2.y * c.y + x1.y * s.y;
    o1.z = x1.z * c.z - x2.z * s.z;  o2.z = x2.z * c.z + x1.z * s.z;
    o1.w = x1.w * c.w - x2.w * s.w;  o2.w = x2.w * c.w + x1.w * s.w;
}

__global__ __launch_bounds__(256) void k_flash4() {
    extern __shared__ __half hsm[];
    __half* Qh = hsm;
    __half* Ql = Qh + 128 * FS;
    __half* Kh = Ql + 128 * FS;
    __half* Kl = Kh + 64 * FS;
    __half* Vh = Kl + 64 * FS;
    __half* Vl = Vh + 64 * FS;

    const int tid = threadIdx.x;
    const int w = tid >> 5, lane = tid & 31;
    const int g = lane >> 2, tq = lane & 3;
    const int head = blockIdx.y, kvh = head >> 2;
    const int qb = (int)(gridDim.x - 1 - blockIdx.x);   // long tasks first
    const int q0 = qb * 128;

    // ---- load Q with fused RoPE + fp16 split
    for (int idx = tid; idx < 128 * 16; idx += 256) {
        int r = idx >> 4, cq = (idx & 15) << 2;
        int t = q0 + r;
        const float* base = g_qkv + (size_t)t * QKVO + head * HDIM;
        float4 x1 = *(const float4*)&base[cq];
        float4 x2 = *(const float4*)&base[64 + cq];
        float4 cc = *(const float4*)&g_cos[t * 64 + cq];
        float4 ss = *(const float4*)&g_sin[t * 64 + cq];
        float4 o1, o2; rope4(x1, x2, cc, ss, o1, o2);
        uint2 hi, lo;
        split4(o1, hi, lo);
        *(uint2*)&Qh[r * FS + cq] = hi;      *(uint2*)&Ql[r * FS + cq] = lo;
        split4(o2, hi, lo);
        *(uint2*)&Qh[r * FS + 64 + cq] = hi; *(uint2*)&Ql[r * FS + 64 + cq] = lo;
    }

    const int l7 = lane & 7, sel = lane >> 3;
    uint32_t aQh = s2u(Qh) + ((16 * w + (sel & 1) * 8 + l7) * FS + (sel >> 1) * 8) * 2;
    uint32_t aQl = aQh + 128 * FS * 2;
    uint32_t aKh = s2u(Kh) + (((sel >> 1) * 8 + l7) * FS + (sel & 1) * 8) * 2;
    uint32_t aKl = aKh + 64 * FS * 2;
    uint32_t aVh = s2u(Vh) + (((sel & 1) * 8 + l7) * FS + (sel >> 1) * 8) * 2;
    uint32_t aVl = aVh + 64 * FS * 2;

    float m0r = -INFINITY, m1r = -INFINITY, l0r = 0.f, l1r = 0.f;
    float O[16][4];
#pragma unroll
    for (int t = 0; t < 16; t++) { O[t][0]=0.f; O[t][1]=0.f; O[t][2]=0.f; O[t][3]=0.f; }

    const int rowg = q0 + 16 * w + g;
    const int nkb = 2 * qb + 2;

    for (int kb = 0; kb < nkb; kb++) {
        int k0 = kb * 64;
        __syncthreads();
        // ---- K with fused RoPE
        for (int idx = tid; idx < 64 * 16; idx += 256) {
            int r = idx >> 4, cq = (idx & 15) << 2;
            int t = k0 + r;
            const float* base = g_qkv + (size_t)t * QKVO + (NHQ + kvh) * HDIM;
            float4 x1 = *(const float4*)&base[cq];
            float4 x2 = *(const float4*)&base[64 + cq];
            float4 cc = *(const float4*)&g_cos[t * 64 + cq];
            float4 ss = *(const float4*)&g_sin[t * 64 + cq];
            float4 o1, o2; rope4(x1, x2, cc, ss, o1, o2);
            uint2 hi, lo;
            split4(o1, hi, lo);
            *(uint2*)&Kh[r * FS + cq] = hi;      *(uint2*)&Kl[r * FS + cq] = lo;
            split4(o2, hi, lo);
            *(uint2*)&Kh[r * FS + 64 + cq] = hi; *(uint2*)&Kl[r * FS + 64 + cq] = lo;
        }
        // ---- V (no rope)
        for (int idx = tid; idx < 64 * 32; idx += 256) {
            int r = idx >> 5, c = (idx & 31) << 2;
            const float* vbase = g_qkv + (size_t)(k0 + r) * QKVO + (NHQ + NKVH) * HDIM + kvh * HDIM;
            float4 v4 = *(const float4*)&vbase[c];
            uint2 hi, lo; split4(v4, hi, lo);
            *(uint2*)&Vh[r * FS + c] = hi;  *(uint2*)&Vl[r * FS + c] = lo;
        }
        __syncthreads();

        // ---- S = Q K^T (split fp16)
        float sc[8][4];
#pragma unroll
        for (int j = 0; j < 8; j++) { sc[j][0]=0.f; sc[j][1]=0.f; sc[j][2]=0.f; sc[j][3]=0.f; }
#pragma unroll
        for (int kt = 0; kt < 8; kt++) {
            uint32_t qa[4], ql_[4], kh[4], kl_[4];
            ldsm4(qa[0], qa[1], qa[2], qa[3], aQh + 32 * kt);
            ldsm4(ql_[0], ql_[1], ql_[2], ql_[3], aQl + 32 * kt);
#pragma unroll
            for (int p = 0; p < 4; p++) {
                ldsm4(kh[0], kh[1], kh[2], kh[3], aKh + 4352 * p + 32 * kt);
                ldsm4(kl_[0], kl_[1], kl_[2], kl_[3], aKl + 4352 * p + 32 * kt);
                mmaf16(sc[2 * p],     qa,  kh[0], kh[1]);
                mmaf16(sc[2 * p],     qa,  kl_[0], kl_[1]);
                mmaf16(sc[2 * p],     ql_, kh[0], kh[1]);
                mmaf16(sc[2 * p + 1], qa,  kh[2], kh[3]);
                mmaf16(sc[2 * p + 1], qa,  kl_[2], kl_[3]);
                mmaf16(sc[2 * p + 1], ql_, kh[2], kh[3]);
            }
        }

        // ---- scale + causal mask
        bool tail = (kb >= 2 * qb);
#pragma unroll
        for (int j = 0; j < 8; j++) {
            int cb = k0 + 8 * j + 2 * tq;
#pragma unroll
            for (int e = 0; e < 2; e++) {
                float v0 = sc[j][e] * SCALE_QK;
                float v1 = sc[j][2 + e] * SCALE_QK;
                if (tail) {
                    if (cb + e > rowg)     v0 = -INFINITY;
                    if (cb + e > rowg + 8) v1 = -INFINITY;
                }
                sc[j][e] = v0; sc[j][2 + e] = v1;
            }
        }

        // ---- online softmax (rows g, g+8; reduce over tq quad)
        float mx0 = -INFINITY, mx1 = -INFINITY;
#pragma unroll
        for (int j = 0; j < 8; j++) {
            mx0 = fmaxf(mx0, fmaxf(sc[j][0], sc[j][1]));
            mx1 = fmaxf(mx1, fmaxf(sc[j][2], sc[j][3]));
        }
        mx0 = fmaxf(mx0, __shfl_xor_sync(0xffffffffu, mx0, 1));
        mx0 = fmaxf(mx0, __shfl_xor_sync(0xffffffffu, mx0, 2));
        mx1 = fmaxf(mx1, __shfl_xor_sync(0xffffffffu, mx1, 1));
        mx1 = fmaxf(mx1, __shfl_xor_sync(0xffffffffu, mx1, 2));
        float mn0 = fmaxf(m0r, mx0), mn1 = fmaxf(m1r, mx1);
        float c0 = __expf(m0r - mn0), c1 = __expf(m1r - mn1);
        m0r = mn0; m1r = mn1;
        float s0 = 0.f, s1 = 0.f;
#pragma unroll
        for (int j = 0; j < 8; j++) {
            sc[j][0] = __expf(sc[j][0] - mn0) * 1024.0f;
            sc[j][1] = __expf(sc[j][1] - mn0) * 1024.0f;
            sc[j][2] = __expf(sc[j][2] - mn1) * 1024.0f;
            sc[j][3] = __expf(sc[j][3] - mn1) * 1024.0f;
            s0 += sc[j][0] + sc[j][1];
            s1 += sc[j][2] + sc[j][3];
        }
        s0 += __shfl_xor_sync(0xffffffffu, s0, 1);
        s0 += __shfl_xor_sync(0xffffffffu, s0, 2);
        s1 += __shfl_xor_sync(0xffffffffu, s1, 1);
        s1 += __shfl_xor_sync(0xffffffffu, s1, 2);
        l0r = l0r * c0 + s0;
        l1r = l1r * c1 + s1;
#pragma unroll
        for (int t = 0; t < 16; t++) { O[t][0] *= c0; O[t][1] *= c0; O[t][2] *= c1; O[t][3] *= c1; }

        // ---- PV: P C-frags remap directly onto A-frags
#pragma unroll
        for (int jj = 0; jj < 4; jj++) {
            uint32_t pa[4], pl[4];
            splitp(sc[2 * jj][0],     sc[2 * jj][1],     pa[0], pl[0]);
            splitp(sc[2 * jj][2],     sc[2 * jj][3],     pa[1], pl[1]);
            splitp(sc[2 * jj + 1][0], sc[2 * jj + 1][1], pa[2], pl[2]);
            splitp(sc[2 * jj + 1][2], sc[2 * jj + 1][3], pa[3], pl[3]);
#pragma unroll
            for (int q = 0; q < 8; q++) {
                uint32_t vh[4], vl_[4];
                ldsm4t(vh[0], vh[1], vh[2], vh[3], aVh + 4352 * jj + 32 * q);
                ldsm4t(vl_[0], vl_[1], vl_[2], vl_[3], aVl + 4352 * jj + 32 * q);
                mmaf16(O[2 * q],     pa, vh[0], vh[1]);
                mmaf16(O[2 * q],     pa, vl_[0], vl_[1]);
                mmaf16(O[2 * q],     pl, vh[0], vh[1]);
                mmaf16(O[2 * q + 1], pa, vh[2], vh[3]);
                mmaf16(O[2 * q + 1], pa, vl_[2], vl_[3]);
                mmaf16(O[2 * q + 1], pl, vh[2], vh[3]);
            }
        }
    }

    // ---- epilogue: O / l -> g_attn
#pragma unroll
    for (int t = 0; t < 16; t++) {
        int col = head * HDIM + 8 * t + 2 * tq;
        float2 u;
        u.x = O[t][0] / l0r;  u.y = O[t][1] / l0r;
        *(float2*)&g_attn[(size_t)rowg * HIDN + col] = u;
        u.x = O[t][2] / l1r;  u.y = O[t][3] / l1r;
        *(float2*)&g_attn[(size_t)(rowg + 8) * HIDN + col] = u;
    }
}

// ---------------- dynamic quant with sum ----------------
__global__ __launch_bounds__(256) void k_quant() {
    __shared__ float xrow[HIDN];
    __shared__ float red[256];
    int t = blockIdx.x, tid = threadIdx.x;
    const float* src = g_attn + (size_t)t * HIDN;
    float amax = 0.f;
    for (int c = tid; c < HIDN; c += 256) { float x = src[c]; xrow[c] = x; amax = fmaxf(amax, fabsf(x)); }
    red[tid] = amax; __syncthreads();
    for (int k = 128; k > 0; k >>= 1) { if (tid < k) red[tid] = fmaxf(red[tid], red[tid + k]); __syncthreads(); }
    float s = fmaxf(red[0], 1e-8f) / 127.0f;
    __nv_bfloat16* q = g_q2 + (size_t)t * HIDN;
    float qs = 0.f;
    for (int c = tid; c < HIDN; c += 256) {
        float v = rintf(xrow[c] / s);
        v = fminf(fmaxf(v, -127.f), 127.f);
        q[c] = __float2bfloat16(v);
        qs += v;
    }
    __syncthreads();
    red[tid] = qs; __syncthreads();
    for (int k = 128; k > 0; k >>= 1) { if (tid < k) red[tid] += red[tid + k]; __syncthreads(); }
    if (tid == 0) { g_s2[t] = s; g_sum2[t] = red[0]; }
}

// ---------------- launch ----------------
extern "C" void kernel_launch(void* const* d_in, const int* in_sizes, int n_in,
                              void* d_out, int out_size) {
    const int*   positions   = (const int*)d_in[0];
    const int*   q_act       = (const int*)d_in[1];
    const float* act_scale   = (const float*)d_in[2];
    const int*   w_qkv_q     = (const int*)d_in[3];
    const float* w_qkv_scale = (const float*)d_in[4];
    const float* w_qkv_zero  = (const float*)d_in[5];
    const int*   w_o_q       = (const int*)d_in[6];
    const float* w_o_scale   = (const float*)d_in[7];
    const float* w_o_zero    = (const float*)d_in[8];
    float* out = (float*)d_out;

    __nv_bfloat16 *A, *Wqkv, *Wo, *q2;
    float *asum, *qkv, *s2, *sum2;
    cudaGetSymbolAddress((void**)&A,    g_A);
    cudaGetSymbolAddress((void**)&Wqkv, g_Wqkv);
    cudaGetSymbolAddress((void**)&Wo,   g_Wo);
    cudaGetSymbolAddress((void**)&q2,   g_q2);
    cudaGetSymbolAddress((void**)&asum, g_asum);
    cudaGetSymbolAddress((void**)&qkv,  g_qkv);
    cudaGetSymbolAddress((void**)&s2,   g_s2);
    cudaGetSymbolAddress((void**)&sum2, g_sum2);

    cudaFuncSetAttribute(k_flash4, cudaFuncAttributeMaxDynamicSharedMemorySize, FLASH_SMEM4);
    cudaFuncSetAttribute(k_gemm,   cudaFuncAttributeMaxDynamicSharedMemorySize, GEMM_SMEM);

    k_rope_tab<<<TT, 64>>>(positions);
    k_prep_a<<<TT, 256>>>(q_act);
    k_conv_w<<<2048, 256>>>(w_qkv_q, Wqkv, QKVO * HIDN);

    dim3 g1(QKVO / 128, TT / 256);
    k_gemm<<<g1, 512, GEMM_SMEM>>>(A, Wqkv, qkv, TT, QKVO, HIDN, act_scale, asum, w_qkv_scale, w_qkv_zero);

    dim3 g3(TT / 128, NHQ);
    k_flash4<<<g3, 256, FLASH_SMEM4>>>();

    k_quant<<<TT, 256>>>();

    k_conv_w<<<2048, 256>>>(w_o_q, Wo, HIDN * HIDN);

    dim3 g4(HIDN / 128, TT / 256);
    k_gemm<<<g4, 512, GEMM_SMEM>>>(q2, Wo, out, TT, HIDN, HIDN, s2, sum2, w_o_scale, w_o_zero);
}

// round 14
// speedup vs baseline: 1.0475x; 1.0475x over previous
#include <cuda_runtime.h>
#include <cuda_bf16.h>
#include <cuda_fp16.h>
#include <math.h>
#include <float.h>
#include <stdint.h>

#define TT 2048
#define HIDN 4096
#define NHQ 32
#define NKVH 8
#define HDIM 128
#define QKVO 6144
#define SCALE_QK 0.08838834764831845f

// ---------------- device scratch (static; no cudaMalloc) ----------------
static __device__ __nv_bfloat16 g_A[(size_t)TT * HIDN];
static __device__ float         g_asum[TT];
static __device__ __nv_bfloat16 g_Wqkv[(size_t)QKVO * HIDN];
static __device__ __nv_bfloat16 g_Wo[(size_t)HIDN * HIDN];
static __device__ float         g_qkv[(size_t)TT * QKVO];
static __device__ float         g_qr[(size_t)NHQ * TT * HDIM];   // [h][t][d]
static __device__ float         g_kr[(size_t)NKVH * TT * HDIM];  // [kvh][t][d]
static __device__ float         g_attn[(size_t)TT * HIDN];
static __device__ __nv_bfloat16 g_q2[(size_t)TT * HIDN];
static __device__ float         g_s2[TT];
static __device__ float         g_sum2[TT];
static __device__ float         g_cos[TT * 64];
static __device__ float         g_sin[TT * 64];

__device__ __forceinline__ uint32_t s2u(const void* p) { return (uint32_t)__cvta_generic_to_shared(p); }

// ---------------- RoPE table (fp64 inner) ----------------
__global__ void k_rope_tab(const int* __restrict__ pos) {
    int t = blockIdx.x, i = threadIdx.x;               // i: 0..63
    float ef = (float)(2 * i) / 128.0f;
    float invf = (float)(1.0 / pow(10000.0, (double)ef));
    float fr = (float)pos[t] * invf;                   // fp32 mul = reference rounding
    g_cos[t * 64 + i] = (float)cos((double)fr);
    g_sin[t * 64 + i] = (float)sin((double)fr);
}

// ---------------- activation prep ----------------
__global__ void k_prep_a(const int* __restrict__ qa) {
    int t = blockIdx.x, tid = threadIdx.x;
    const int* row = qa + (size_t)t * HIDN;
    __nv_bfloat16* arow = g_A + (size_t)t * HIDN;
    int s = 0;
    for (int c = tid; c < HIDN; c += 256) { int v = row[c]; s += v; arow[c] = __float2bfloat16((float)v); }
    __shared__ int red[256];
    red[tid] = s; __syncthreads();
    for (int k = 128; k > 0; k >>= 1) { if (tid < k) red[tid] += red[tid + k]; __syncthreads(); }
    if (tid == 0) g_asum[t] = (float)red[0];
}

__global__ void k_conv_w(const int* __restrict__ w, __nv_bfloat16* __restrict__ o, int n) {
    int i = blockIdx.x * blockDim.x + threadIdx.x;
    int stride = gridDim.x * blockDim.x;
    for (int v = i; v < n / 4; v += stride) {
        int4 x = ((const int4*)w)[v];
        __nv_bfloat162 p0 = {__float2bfloat16((float)x.x), __float2bfloat16((float)x.y)};
        __nv_bfloat162 p1 = {__float2bfloat16((float)x.z), __float2bfloat16((float)x.w)};
        ((__nv_bfloat162*)o)[2 * v] = p0;
        ((__nv_bfloat162*)o)[2 * v + 1] = p1;
    }
}

// ==================================================================
// bf16 HMMA GEMM v3 (R9/R10 measured-best): CTA 256x128, warp 64x64,
// 3-stage cp.async pipeline, ldmatrix fragments, fused W4A8 epilogue.
// ==================================================================
#define GST 40
#define ASTG (256 * GST)
#define BSTG (128 * GST)
#define GEMM_SMEM (3 * (ASTG + BSTG) * 2)

__device__ __forceinline__ void ldsm4(uint32_t& r0, uint32_t& r1, uint32_t& r2, uint32_t& r3, uint32_t a) {
    asm volatile("ldmatrix.sync.aligned.m8n8.x4.shared.b16 {%0,%1,%2,%3},[%4];\n"
                 : "=r"(r0), "=r"(r1), "=r"(r2), "=r"(r3) : "r"(a));
}
__device__ __forceinline__ void mmabf(float* c, const uint32_t* a, uint32_t b0, uint32_t b1) {
    asm volatile("mma.sync.aligned.m16n8k16.row.col.f32.bf16.bf16.f32 "
                 "{%0,%1,%2,%3},{%4,%5,%6,%7},{%8,%9},{%0,%1,%2,%3};\n"
                 : "+f"(c[0]), "+f"(c[1]), "+f"(c[2]), "+f"(c[3])
                 : "r"(a[0]), "r"(a[1]), "r"(a[2]), "r"(a[3]), "r"(b0), "r"(b1));
}
#define CP16(dst, src) asm volatile("cp.async.cg.shared.global [%0], [%1], 16;\n" :: "r"(dst), "l"(src))
#define CPCOMMIT()     asm volatile("cp.async.commit_group;\n")
#define CPWAIT1()      asm volatile("cp.async.wait_group 1;\n" ::: "memory")

__global__ __launch_bounds__(256, 1) void k_gemm(
    const __nv_bfloat16* __restrict__ A, const __nv_bfloat16* __restrict__ B,
    float* __restrict__ C, int M, int N, int K,
    const float* __restrict__ rs, const float* __restrict__ rsum,
    const float* __restrict__ cs, const float* __restrict__ cz)
{
    extern __shared__ __nv_bfloat16 gsm[];
    __nv_bfloat16* Ash = gsm;
    __nv_bfloat16* Bsh = gsm + 3 * ASTG;

    const int tid = threadIdx.x;
    const int warp = tid >> 5, lane = tid & 31;
    const int wm = warp >> 1, wn = warp & 1;
    const int g = lane >> 2, tq = lane & 3;
    const int sel = lane >> 3, l7 = lane & 7;
    const int bm0 = blockIdx.y * 256, bn0 = blockIdx.x * 128;

    const int r0 = tid >> 2, c0 = (tid & 3) * 8;
    const __nv_bfloat16* Abase = A + (size_t)(bm0 + r0) * K + c0;
    const __nv_bfloat16* Bbase = B + (size_t)(bn0 + r0) * K + c0;
    const size_t rowK64 = (size_t)64 * K;

    uint32_t sA = s2u(Ash), sB = s2u(Bsh);
    uint32_t dA = sA + (r0 * GST + c0) * 2;
    uint32_t dB = sB + (r0 * GST + c0) * 2;

    uint32_t aA = sA + ((wm * 64 + (sel & 1) * 8 + l7) * GST + (sel >> 1) * 8) * 2;
    uint32_t aB = sB + ((wn * 64 + (sel >> 1) * 8 + l7) * GST + (sel & 1) * 8) * 2;

    float acc[4][8][4];
#pragma unroll
    for (int i = 0; i < 4; i++)
#pragma unroll
        for (int j = 0; j < 8; j++) { acc[i][j][0]=0.f; acc[i][j][1]=0.f; acc[i][j][2]=0.f; acc[i][j][3]=0.f; }

    const int KT = K >> 5;

#pragma unroll
    for (int s = 0; s < 2; s++) {
        const __nv_bfloat16* Ak = Abase + s * 32;
        const __nv_bfloat16* Bk = Bbase + s * 32;
        uint32_t oA = dA + s * ASTG * 2, oB = dB + s * BSTG * 2;
#pragma unroll
        for (int q = 0; q < 4; q++) CP16(oA + q * 64 * GST * 2, Ak + q * rowK64);
#pragma unroll
        for (int q = 0; q < 2; q++) CP16(oB + q * 64 * GST * 2, Bk + q * rowK64);
        CPCOMMIT();
    }
    CPWAIT1();
    __syncthreads();

    for (int kb = 0; kb < KT; kb++) {
        const int st = kb % 3;
        if (kb + 2 < KT) {
            const int ns = (kb + 2) % 3;
            const __nv_bfloat16* Ak = Abase + (kb + 2) * 32;
            const __nv_bfloat16* Bk = Bbase + (kb + 2) * 32;
            uint32_t oA = dA + ns * ASTG * 2, oB = dB + ns * BSTG * 2;
#pragma unroll
            for (int q = 0; q < 4; q++) CP16(oA + q * 64 * GST * 2, Ak + q * rowK64);
#pragma unroll
            for (int q = 0; q < 2; q++) CP16(oB + q * 64 * GST * 2, Bk + q * rowK64);
            CPCOMMIT();
        }
        const uint32_t stA = aA + st * ASTG * 2;
        const uint32_t stB = aB + st * BSTG * 2;
#pragma unroll
        for (int ks = 0; ks < 2; ks++) {
            uint32_t af[4][4], bf[4][4];
#pragma unroll
            for (int mi = 0; mi < 4; mi++)
                ldsm4(af[mi][0], af[mi][1], af[mi][2], af[mi][3], stA + mi * 16 * GST * 2 + ks * 32);
#pragma unroll
            for (int p = 0; p < 4; p++)
                ldsm4(bf[p][0], bf[p][1], bf[p][2], bf[p][3], stB + p * 16 * GST * 2 + ks * 32);
#pragma unroll
            for (int mi = 0; mi < 4; mi++)
#pragma unroll
                for (int p = 0; p < 4; p++) {
                    mmabf(acc[mi][2 * p],     af[mi], bf[p][0], bf[p][1]);
                    mmabf(acc[mi][2 * p + 1], af[mi], bf[p][2], bf[p][3]);
                }
        }
        if (kb + 1 < KT) {
            CPWAIT1();
            __syncthreads();
        }
    }

#pragma unroll
    for (int mi = 0; mi < 4; mi++) {
        int rA = bm0 + wm * 64 + mi * 16 + g;
        int rB = rA + 8;
        float rsA = rs[rA], rmA = rsum[rA];
        float rsB = rs[rB], rmB = rsum[rB];
#pragma unroll
        for (int ni = 0; ni < 8; ni++) {
            int col = bn0 + wn * 64 + ni * 8 + 2 * tq;
            float cs0 = cs[col], cs1 = cs[col + 1];
            float cz0 = cz[col], cz1 = cz[col + 1];
            float2 o0, o1;
            o0.x = (rsA * cs0) * (acc[mi][ni][0] - cz0 * rmA);
            o0.y = (rsA * cs1) * (acc[mi][ni][1] - cz1 * rmA);
            o1.x = (rsB * cs0) * (acc[mi][ni][2] - cz0 * rmB);
            o1.y = (rsB * cs1) * (acc[mi][ni][3] - cz1 * rmB);
            *(float2*)&C[(size_t)rA * N + col] = o0;
            *(float2*)&C[(size_t)rB * N + col] = o1;
        }
    }
}

// ---------------- RoPE apply ----------------
__global__ void k_rope_apply() {
    int t = blockIdx.x, hh = blockIdx.y, i = threadIdx.x;   // i 0..63
    float c = g_cos[t * 64 + i], s = g_sin[t * 64 + i];
    if (hh < NHQ) {
        const float* base = g_qkv + (size_t)t * QKVO + hh * HDIM;
        float x1 = base[i], x2 = base[64 + i];
        float* o = g_qr + (size_t)hh * TT * HDIM + (size_t)t * HDIM;
        o[i] = x1 * c - x2 * s;  o[64 + i] = x2 * c + x1 * s;
    } else {
        int kvh = hh - NHQ;
        const float* base = g_qkv + (size_t)t * QKVO + NHQ * HDIM + kvh * HDIM;
        float x1 = base[i], x2 = base[64 + i];
        float* o = g_kr + (size_t)kvh * TT * HDIM + (size_t)t * HDIM;
        o[i] = x1 * c - x2 * s;  o[64 + i] = x2 * c + x1 * s;
    }
}

// ======================================================================
// fp16 split-precision flash attention (R6/R9 measured-best shape,
// BM=128/BN=64, g_qr inputs) + Q-fragment register hoisting.
// ======================================================================
#define FS 136
#define FLASH_SMEM2 ((128 * FS * 2 + 64 * FS * 4) * 2)

__device__ __forceinline__ void ldsm4t(uint32_t& r0, uint32_t& r1, uint32_t& r2, uint32_t& r3, uint32_t a) {
    asm volatile("ldmatrix.sync.aligned.m8n8.x4.trans.shared.b16 {%0,%1,%2,%3},[%4];\n"
                 : "=r"(r0), "=r"(r1), "=r"(r2), "=r"(r3) : "r"(a));
}
__device__ __forceinline__ void mmaf16(float* c, const uint32_t* a, uint32_t b0, uint32_t b1) {
    asm volatile("mma.sync.aligned.m16n8k16.row.col.f32.f16.f16.f32 "
                 "{%0,%1,%2,%3},{%4,%5,%6,%7},{%8,%9},{%0,%1,%2,%3};\n"
                 : "+f"(c[0]), "+f"(c[1]), "+f"(c[2]), "+f"(c[3])
                 : "r"(a[0]), "r"(a[1]), "r"(a[2]), "r"(a[3]), "r"(b0), "r"(b1));
}
__device__ __forceinline__ uint32_t ph2(__half a, __half b) {
    return (uint32_t)__half_as_ushort(a) | ((uint32_t)__half_as_ushort(b) << 16);
}
__device__ __forceinline__ void split4(float4 v, uint2& hi, uint2& lo) {
    __half a = __float2half_rn(v.x), b = __float2half_rn(v.y);
    __half c = __float2half_rn(v.z), d = __float2half_rn(v.w);
    hi.x = ph2(a, b); hi.y = ph2(c, d);
    lo.x = ph2(__float2half_rn(v.x - __half2float(a)), __float2half_rn(v.y - __half2float(b)));
    lo.y = ph2(__float2half_rn(v.z - __half2float(c)), __float2half_rn(v.w - __half2float(d)));
}
__device__ __forceinline__ void splitp(float x, float y, uint32_t& hi, uint32_t& lo) {
    __half a = __float2half_rn(x), b = __float2half_rn(y);
    hi = ph2(a, b);
    lo = ph2(__float2half_rn(x - __half2float(a)), __float2half_rn(y - __half2float(b)));
}

__global__ __launch_bounds__(256) void k_flash2() {
    extern __shared__ __half hsm[];
    __half* Qh = hsm;
    __half* Ql = Qh + 128 * FS;
    __half* Kh = Ql + 128 * FS;
    __half* Kl = Kh + 64 * FS;
    __half* Vh = Kl + 64 * FS;
    __half* Vl = Vh + 64 * FS;

    const int tid = threadIdx.x;
    const int w = tid >> 5, lane = tid & 31;
    const int g = lane >> 2, tq = lane & 3;
    const int head = blockIdx.y, kvh = head >> 2;
    const int qb = (int)(gridDim.x - 1 - blockIdx.x);
    const int q0 = qb * 128;

    const float* Qg = g_qr + (size_t)head * TT * HDIM + (size_t)q0 * HDIM;
    for (int idx = tid; idx < 128 * 32; idx += 256) {
        int r = idx >> 5, c = (idx & 31) << 2;
        float4 v = *(const float4*)&Qg[(size_t)r * HDIM + c];
        uint2 hi, lo; split4(v, hi, lo);
        *(uint2*)&Qh[r * FS + c] = hi;
        *(uint2*)&Ql[r * FS + c] = lo;
    }

    const int l7 = lane & 7, sel = lane >> 3;
    uint32_t aQh = s2u(Qh) + ((16 * w + (sel & 1) * 8 + l7) * FS + (sel >> 1) * 8) * 2;
    uint32_t aQl = aQh + 128 * FS * 2;
    uint32_t aKh = s2u(Kh) + (((sel >> 1) * 8 + l7) * FS + (sel & 1) * 8) * 2;
    uint32_t aKl = aKh + 64 * FS * 2;
    uint32_t aVh = s2u(Vh) + (((sel & 1) * 8 + l7) * FS + (sel >> 1) * 8) * 2;
    uint32_t aVl = aVh + 64 * FS * 2;

    __syncthreads();
    // ---- hoist Q fragments (tile-invariant) into registers
    uint32_t qfh[8][4], qfl[8][4];
#pragma unroll
    for (int kt = 0; kt < 8; kt++) {
        ldsm4(qfh[kt][0], qfh[kt][1], qfh[kt][2], qfh[kt][3], aQh + 32 * kt);
        ldsm4(qfl[kt][0], qfl[kt][1], qfl[kt][2], qfl[kt][3], aQl + 32 * kt);
    }

    float m0r = -INFINITY, m1r = -INFINITY, l0r = 0.f, l1r = 0.f;
    float O[16][4];
#pragma unroll
    for (int t = 0; t < 16; t++) { O[t][0]=0.f; O[t][1]=0.f; O[t][2]=0.f; O[t][3]=0.f; }

    const float* Kg = g_kr + (size_t)kvh * TT * HDIM;
    const float* Vg = g_qkv + (NHQ + NKVH) * HDIM + kvh * HDIM;
    const int rowg = q0 + 16 * w + g;
    const int nkb = 2 * qb + 2;

    for (int kb = 0; kb < nkb; kb++) {
        int k0 = kb * 64;
        __syncthreads();
        for (int idx = tid; idx < 64 * 32; idx += 256) {
            int r = idx >> 5, c = (idx & 31) << 2;
            uint2 hi, lo;
            float4 kv4 = *(const float4*)&Kg[(size_t)(k0 + r) * HDIM + c];
            split4(kv4, hi, lo);
            *(uint2*)&Kh[r * FS + c] = hi;  *(uint2*)&Kl[r * FS + c] = lo;
            float4 vv4 = *(const float4*)&Vg[(size_t)(k0 + r) * QKVO + c];
            split4(vv4, hi, lo);
            *(uint2*)&Vh[r * FS + c] = hi;  *(uint2*)&Vl[r * FS + c] = lo;
        }
        __syncthreads();

        float sc[8][4];
#pragma unroll
        for (int j = 0; j < 8; j++) { sc[j][0]=0.f; sc[j][1]=0.f; sc[j][2]=0.f; sc[j][3]=0.f; }
#pragma unroll
        for (int kt = 0; kt < 8; kt++) {
            uint32_t kh[4], kl_[4];
#pragma unroll
            for (int p = 0; p < 4; p++) {
                ldsm4(kh[0], kh[1], kh[2], kh[3], aKh + 4352 * p + 32 * kt);
                ldsm4(kl_[0], kl_[1], kl_[2], kl_[3], aKl + 4352 * p + 32 * kt);
                mmaf16(sc[2 * p],     qfh[kt], kh[0], kh[1]);
                mmaf16(sc[2 * p],     qfh[kt], kl_[0], kl_[1]);
                mmaf16(sc[2 * p],     qfl[kt], kh[0], kh[1]);
                mmaf16(sc[2 * p + 1], qfh[kt], kh[2], kh[3]);
                mmaf16(sc[2 * p + 1], qfh[kt], kl_[2], kl_[3]);
                mmaf16(sc[2 * p + 1], qfl[kt], kh[2], kh[3]);
            }
        }

        bool tail = (kb >= 2 * qb);
#pragma unroll
        for (int j = 0; j < 8; j++) {
            int cb = k0 + 8 * j + 2 * tq;
#pragma unroll
            for (int e = 0; e < 2; e++) {
                float v0 = sc[j][e] * SCALE_QK;
                float v1 = sc[j][2 + e] * SCALE_QK;
                if (tail) {
                    if (cb + e > rowg)     v0 = -INFINITY;
                    if (cb + e > rowg + 8) v1 = -INFINITY;
                }
                sc[j][e] = v0; sc[j][2 + e] = v1;
            }
        }

        float mx0 = -INFINITY, mx1 = -INFINITY;
#pragma unroll
        for (int j = 0; j < 8; j++) {
            mx0 = fmaxf(mx0, fmaxf(sc[j][0], sc[j][1]));
            mx1 = fmaxf(mx1, fmaxf(sc[j][2], sc[j][3]));
        }
        mx0 = fmaxf(mx0, __shfl_xor_sync(0xffffffffu, mx0, 1));
        mx0 = fmaxf(mx0, __shfl_xor_sync(0xffffffffu, mx0, 2));
        mx1 = fmaxf(mx1, __shfl_xor_sync(0xffffffffu, mx1, 1));
        mx1 = fmaxf(mx1, __shfl_xor_sync(0xffffffffu, mx1, 2));
        float mn0 = fmaxf(m0r, mx0), mn1 = fmaxf(m1r, mx1);
        float c0 = __expf(m0r - mn0), c1 = __expf(m1r - mn1);
        m0r = mn0; m1r = mn1;
        float s0 = 0.f, s1 = 0.f;
#pragma unroll
        for (int j = 0; j < 8; j++) {
            sc[j][0] = __expf(sc[j][0] - mn0) * 1024.0f;
            sc[j][1] = __expf(sc[j][1] - mn0) * 1024.0f;
            sc[j][2] = __expf(sc[j][2] - mn1) * 1024.0f;
            sc[j][3] = __expf(sc[j][3] - mn1) * 1024.0f;
            s0 += sc[j][0] + sc[j][1];
            s1 += sc[j][2] + sc[j][3];
        }
        s0 += __shfl_xor_sync(0xffffffffu, s0, 1);
        s0 += __shfl_xor_sync(0xffffffffu, s0, 2);
        s1 += __shfl_xor_sync(0xffffffffu, s1, 1);
        s1 += __shfl_xor_sync(0xffffffffu, s1, 2);
        l0r = l0r * c0 + s0;
        l1r = l1r * c1 + s1;
#pragma unroll
        for (int t = 0; t < 16; t++) { O[t][0] *= c0; O[t][1] *= c0; O[t][2] *= c1; O[t][3] *= c1; }

#pragma unroll
        for (int jj = 0; jj < 4; jj++) {
            uint32_t pa[4], pl[4];
            splitp(sc[2 * jj][0],     sc[2 * jj][1],     pa[0], pl[0]);
            splitp(sc[2 * jj][2],     sc[2 * jj][3],     pa[1], pl[1]);
            splitp(sc[2 * jj + 1][0], sc[2 * jj + 1][1], pa[2], pl[2]);
            splitp(sc[2 * jj + 1][2], sc[2 * jj + 1][3], pa[3], pl[3]);
#pragma unroll
            for (int q = 0; q < 8; q++) {
                uint32_t vh[4], vl_[4];
                ldsm4t(vh[0], vh[1], vh[2], vh[3], aVh + 4352 * jj + 32 * q);
                ldsm4t(vl_[0], vl_[1], vl_[2], vl_[3], aVl + 4352 * jj + 32 * q);
                mmaf16(O[2 * q],     pa, vh[0], vh[1]);
                mmaf16(O[2 * q],     pa, vl_[0], vl_[1]);
                mmaf16(O[2 * q],     pl, vh[0], vh[1]);
                mmaf16(O[2 * q + 1], pa, vh[2], vh[3]);
                mmaf16(O[2 * q + 1], pa, vl_[2], vl_[3]);
                mmaf16(O[2 * q + 1], pl, vh[2], vh[3]);
            }
        }
    }

#pragma unroll
    for (int t = 0; t < 16; t++) {
        int col = head * HDIM + 8 * t + 2 * tq;
        float2 u;
        u.x = O[t][0] / l0r;  u.y = O[t][1] / l0r;
        *(float2*)&g_attn[(size_t)rowg * HIDN + col] = u;
        u.x = O[t][2] / l1r;  u.y = O[t][3] / l1r;
        *(float2*)&g_attn[(size_t)(rowg + 8) * HIDN + col] = u;
    }
}

// ---------------- dynamic quant with sum (reciprocal hoisted) ----------------
__global__ __launch_bounds__(256) void k_quant() {
    __shared__ float xrow[HIDN];
    __shared__ float red[256];
    int t = blockIdx.x, tid = threadIdx.x;
    const float* src = g_attn + (size_t)t * HIDN;
    float amax = 0.f;
    for (int c = tid; c < HIDN; c += 256) { float x = src[c]; xrow[c] = x; amax = fmaxf(amax, fabsf(x)); }
    red[tid] = amax; __syncthreads();
    for (int k = 128; k > 0; k >>= 1) { if (tid < k) red[tid] = fmaxf(red[tid], red[tid + k]); __syncthreads(); }
    float s = fmaxf(red[0], 1e-8f) / 127.0f;
    float sinv = 1.0f / s;                 // exact-div once; per-element mul (<=1ulp vs div)
    __nv_bfloat16* q = g_q2 + (size_t)t * HIDN;
    float qs = 0.f;
    for (int c = tid; c < HIDN; c += 256) {
        float v = rintf(xrow[c] * sinv);
        v = fminf(fmaxf(v, -127.f), 127.f);
        q[c] = __float2bfloat16(v);
        qs += v;
    }
    __syncthreads();
    red[tid] = qs; __syncthreads();
    for (int k = 128; k > 0; k >>= 1) { if (tid < k) red[tid] += red[tid + k]; __syncthreads(); }
    if (tid == 0) { g_s2[t] = s; g_sum2[t] = red[0]; }
}

// ---------------- launch ----------------
extern "C" void kernel_launch(void* const* d_in, const int* in_sizes, int n_in,
                              void* d_out, int out_size) {
    const int*   positions   = (const int*)d_in[0];
    const int*   q_act       = (const int*)d_in[1];
    const float* act_scale   = (const float*)d_in[2];
    const int*   w_qkv_q     = (const int*)d_in[3];
    const float* w_qkv_scale = (const float*)d_in[4];
    const float* w_qkv_zero  = (const float*)d_in[5];
    const int*   w_o_q       = (const int*)d_in[6];
    const float* w_o_scale   = (const float*)d_in[7];
    const float* w_o_zero    = (const float*)d_in[8];
    float* out = (float*)d_out;

    __nv_bfloat16 *A, *Wqkv, *Wo, *q2;
    float *asum, *qkv, *s2, *sum2;
    cudaGetSymbolAddress((void**)&A,    g_A);
    cudaGetSymbolAddress((void**)&Wqkv, g_Wqkv);
    cudaGetSymbolAddress((void**)&Wo,   g_Wo);
    cudaGetSymbolAddress((void**)&q2,   g_q2);
    cudaGetSymbolAddress((void**)&asum, g_asum);
    cudaGetSymbolAddress((void**)&qkv,  g_qkv);
    cudaGetSymbolAddress((void**)&s2,   g_s2);
    cudaGetSymbolAddress((void**)&sum2, g_sum2);

    cudaFuncSetAttribute(k_flash2, cudaFuncAttributeMaxDynamicSharedMemorySize, FLASH_SMEM2);
    cudaFuncSetAttribute(k_gemm,   cudaFuncAttributeMaxDynamicSharedMemorySize, GEMM_SMEM);

    k_rope_tab<<<TT, 64>>>(positions);
    k_prep_a<<<TT, 256>>>(q_act);
    k_conv_w<<<2048, 256>>>(w_qkv_q, Wqkv, QKVO * HIDN);

    dim3 g1(QKVO / 128, TT / 256);
    k_gemm<<<g1, 256, GEMM_SMEM>>>(A, Wqkv, qkv, TT, QKVO, HIDN, act_scale, asum, w_qkv_scale, w_qkv_zero);

    dim3 g2(TT, NHQ + NKVH);
    k_rope_apply<<<g2, 64>>>();

    dim3 g3(TT / 128, NHQ);
    k_flash2<<<g3, 256, FLASH_SMEM2>>>();

    k_quant<<<TT, 256>>>();

    k_conv_w<<<2048, 256>>>(w_o_q, Wo, HIDN * HIDN);

    dim3 g4(HIDN / 128, TT / 256);
    k_gemm<<<g4, 256, GEMM_SMEM>>>(q2, Wo, out, TT, HIDN, HIDN, s2, sum2, w_o_scale, w_o_zero);
}

// round 15
// speedup vs baseline: 1.1493x; 1.0972x over previous
#include <cuda_runtime.h>
#include <cuda_bf16.h>
#include <cuda_fp16.h>
#include <math.h>
#include <float.h>
#include <stdint.h>

#define TT 2048
#define HIDN 4096
#define NHQ 32
#define NKVH 8
#define HDIM 128
#define QKVO 6144
#define SCALE_QK 0.08838834764831845f

// ---------------- device scratch (static; no cudaMalloc) ----------------
static __device__ __nv_bfloat16 g_A[(size_t)TT * HIDN];
static __device__ float         g_asum[TT];
static __device__ __nv_bfloat16 g_Wqkv[(size_t)QKVO * HIDN];
static __device__ __nv_bfloat16 g_Wo[(size_t)HIDN * HIDN];
static __device__ float         g_qkv[(size_t)TT * QKVO];
static __device__ __half        g_qh[(size_t)NHQ * TT * HDIM];   // Q hi  [h][t][d]
static __device__ __half        g_ql[(size_t)NHQ * TT * HDIM];   // Q lo
static __device__ __half        g_kh[(size_t)NKVH * TT * HDIM];  // K hi  [kvh][t][d]
static __device__ __half        g_kl[(size_t)NKVH * TT * HDIM];
static __device__ __half        g_vh[(size_t)NKVH * TT * HDIM];  // V hi
static __device__ __half        g_vl[(size_t)NKVH * TT * HDIM];
static __device__ float         g_attn[(size_t)TT * HIDN];
static __device__ __nv_bfloat16 g_q2[(size_t)TT * HIDN];
static __device__ float         g_s2[TT];
static __device__ float         g_sum2[TT];
static __device__ float         g_cos[TT * 64];
static __device__ float         g_sin[TT * 64];

__device__ __forceinline__ uint32_t s2u(const void* p) { return (uint32_t)__cvta_generic_to_shared(p); }

// ---------------- RoPE table (fp64 inner) ----------------
__global__ void k_rope_tab(const int* __restrict__ pos) {
    int t = blockIdx.x, i = threadIdx.x;               // i: 0..63
    float ef = (float)(2 * i) / 128.0f;
    float invf = (float)(1.0 / pow(10000.0, (double)ef));
    float fr = (float)pos[t] * invf;                   // fp32 mul = reference rounding
    g_cos[t * 64 + i] = (float)cos((double)fr);
    g_sin[t * 64 + i] = (float)sin((double)fr);
}

// ---------------- activation prep ----------------
__global__ void k_prep_a(const int* __restrict__ qa) {
    int t = blockIdx.x, tid = threadIdx.x;
    const int* row = qa + (size_t)t * HIDN;
    __nv_bfloat16* arow = g_A + (size_t)t * HIDN;
    int s = 0;
    for (int c = tid; c < HIDN; c += 256) { int v = row[c]; s += v; arow[c] = __float2bfloat16((float)v); }
    __shared__ int red[256];
    red[tid] = s; __syncthreads();
    for (int k = 128; k > 0; k >>= 1) { if (tid < k) red[tid] += red[tid + k]; __syncthreads(); }
    if (tid == 0) g_asum[t] = (float)red[0];
}

__global__ void k_conv_w(const int* __restrict__ w, __nv_bfloat16* __restrict__ o, int n) {
    int i = blockIdx.x * blockDim.x + threadIdx.x;
    int stride = gridDim.x * blockDim.x;
    for (int v = i; v < n / 4; v += stride) {
        int4 x = ((const int4*)w)[v];
        __nv_bfloat162 p0 = {__float2bfloat16((float)x.x), __float2bfloat16((float)x.y)};
        __nv_bfloat162 p1 = {__float2bfloat16((float)x.z), __float2bfloat16((float)x.w)};
        ((__nv_bfloat162*)o)[2 * v] = p0;
        ((__nv_bfloat162*)o)[2 * v + 1] = p1;
    }
}

// ==================================================================
// bf16 HMMA GEMM v3 (measured-best): CTA 256x128, warp 64x64,
// 3-stage cp.async pipeline, ldmatrix fragments, fused W4A8 epilogue.
// ==================================================================
#define GST 40
#define ASTG (256 * GST)
#define BSTG (128 * GST)
#define GEMM_SMEM (3 * (ASTG + BSTG) * 2)

__device__ __forceinline__ void ldsm4(uint32_t& r0, uint32_t& r1, uint32_t& r2, uint32_t& r3, uint32_t a) {
    asm volatile("ldmatrix.sync.aligned.m8n8.x4.shared.b16 {%0,%1,%2,%3},[%4];\n"
                 : "=r"(r0), "=r"(r1), "=r"(r2), "=r"(r3) : "r"(a));
}
__device__ __forceinline__ void mmabf(float* c, const uint32_t* a, uint32_t b0, uint32_t b1) {
    asm volatile("mma.sync.aligned.m16n8k16.row.col.f32.bf16.bf16.f32 "
                 "{%0,%1,%2,%3},{%4,%5,%6,%7},{%8,%9},{%0,%1,%2,%3};\n"
                 : "+f"(c[0]), "+f"(c[1]), "+f"(c[2]), "+f"(c[3])
                 : "r"(a[0]), "r"(a[1]), "r"(a[2]), "r"(a[3]), "r"(b0), "r"(b1));
}
#define CP16(dst, src) asm volatile("cp.async.cg.shared.global [%0], [%1], 16;\n" :: "r"(dst), "l"(src))
#define CPCOMMIT()     asm volatile("cp.async.commit_group;\n")
#define CPWAIT1()      asm volatile("cp.async.wait_group 1;\n" ::: "memory")
#define CPWAIT0()      asm volatile("cp.async.wait_group 0;\n" ::: "memory")

__global__ __launch_bounds__(256, 1) void k_gemm(
    const __nv_bfloat16* __restrict__ A, const __nv_bfloat16* __restrict__ B,
    float* __restrict__ C, int M, int N, int K,
    const float* __restrict__ rs, const float* __restrict__ rsum,
    const float* __restrict__ cs, const float* __restrict__ cz)
{
    extern __shared__ __nv_bfloat16 gsm[];
    __nv_bfloat16* Ash = gsm;
    __nv_bfloat16* Bsh = gsm + 3 * ASTG;

    const int tid = threadIdx.x;
    const int warp = tid >> 5, lane = tid & 31;
    const int wm = warp >> 1, wn = warp & 1;
    const int g = lane >> 2, tq = lane & 3;
    const int sel = lane >> 3, l7 = lane & 7;
    const int bm0 = blockIdx.y * 256, bn0 = blockIdx.x * 128;

    const int r0 = tid >> 2, c0 = (tid & 3) * 8;
    const __nv_bfloat16* Abase = A + (size_t)(bm0 + r0) * K + c0;
    const __nv_bfloat16* Bbase = B + (size_t)(bn0 + r0) * K + c0;
    const size_t rowK64 = (size_t)64 * K;

    uint32_t sA = s2u(Ash), sB = s2u(Bsh);
    uint32_t dA = sA + (r0 * GST + c0) * 2;
    uint32_t dB = sB + (r0 * GST + c0) * 2;

    uint32_t aA = sA + ((wm * 64 + (sel & 1) * 8 + l7) * GST + (sel >> 1) * 8) * 2;
    uint32_t aB = sB + ((wn * 64 + (sel >> 1) * 8 + l7) * GST + (sel & 1) * 8) * 2;

    float acc[4][8][4];
#pragma unroll
    for (int i = 0; i < 4; i++)
#pragma unroll
        for (int j = 0; j < 8; j++) { acc[i][j][0]=0.f; acc[i][j][1]=0.f; acc[i][j][2]=0.f; acc[i][j][3]=0.f; }

    const int KT = K >> 5;

#pragma unroll
    for (int s = 0; s < 2; s++) {
        const __nv_bfloat16* Ak = Abase + s * 32;
        const __nv_bfloat16* Bk = Bbase + s * 32;
        uint32_t oA = dA + s * ASTG * 2, oB = dB + s * BSTG * 2;
#pragma unroll
        for (int q = 0; q < 4; q++) CP16(oA + q * 64 * GST * 2, Ak + q * rowK64);
#pragma unroll
        for (int q = 0; q < 2; q++) CP16(oB + q * 64 * GST * 2, Bk + q * rowK64);
        CPCOMMIT();
    }
    CPWAIT1();
    __syncthreads();

    for (int kb = 0; kb < KT; kb++) {
        const int st = kb % 3;
        if (kb + 2 < KT) {
            const int ns = (kb + 2) % 3;
            const __nv_bfloat16* Ak = Abase + (kb + 2) * 32;
            const __nv_bfloat16* Bk = Bbase + (kb + 2) * 32;
            uint32_t oA = dA + ns * ASTG * 2, oB = dB + ns * BSTG * 2;
#pragma unroll
            for (int q = 0; q < 4; q++) CP16(oA + q * 64 * GST * 2, Ak + q * rowK64);
#pragma unroll
            for (int q = 0; q < 2; q++) CP16(oB + q * 64 * GST * 2, Bk + q * rowK64);
            CPCOMMIT();
        }
        const uint32_t stA = aA + st * ASTG * 2;
        const uint32_t stB = aB + st * BSTG * 2;
#pragma unroll
        for (int ks = 0; ks < 2; ks++) {
            uint32_t af[4][4], bf[4][4];
#pragma unroll
            for (int mi = 0; mi < 4; mi++)
                ldsm4(af[mi][0], af[mi][1], af[mi][2], af[mi][3], stA + mi * 16 * GST * 2 + ks * 32);
#pragma unroll
            for (int p = 0; p < 4; p++)
                ldsm4(bf[p][0], bf[p][1], bf[p][2], bf[p][3], stB + p * 16 * GST * 2 + ks * 32);
#pragma unroll
            for (int mi = 0; mi < 4; mi++)
#pragma unroll
                for (int p = 0; p < 4; p++) {
                    mmabf(acc[mi][2 * p],     af[mi], bf[p][0], bf[p][1]);
                    mmabf(acc[mi][2 * p + 1], af[mi], bf[p][2], bf[p][3]);
                }
        }
        if (kb + 1 < KT) {
            CPWAIT1();
            __syncthreads();
        }
    }

#pragma unroll
    for (int mi = 0; mi < 4; mi++) {
        int rA = bm0 + wm * 64 + mi * 16 + g;
        int rB = rA + 8;
        float rsA = rs[rA], rmA = rsum[rA];
        float rsB = rs[rB], rmB = rsum[rB];
#pragma unroll
        for (int ni = 0; ni < 8; ni++) {
            int col = bn0 + wn * 64 + ni * 8 + 2 * tq;
            float cs0 = cs[col], cs1 = cs[col + 1];
            float cz0 = cz[col], cz1 = cz[col + 1];
            float2 o0, o1;
            o0.x = (rsA * cs0) * (acc[mi][ni][0] - cz0 * rmA);
            o0.y = (rsA * cs1) * (acc[mi][ni][1] - cz1 * rmA);
            o1.x = (rsB * cs0) * (acc[mi][ni][2] - cz0 * rmB);
            o1.y = (rsB * cs1) * (acc[mi][ni][3] - cz1 * rmB);
            *(float2*)&C[(size_t)rA * N + col] = o0;
            *(float2*)&C[(size_t)rB * N + col] = o1;
        }
    }
}

// ---------------- RoPE + fp16 split for Q and K ----------------
__device__ __forceinline__ void w_split(__half* hp, __half* lp, size_t off, float x) {
    __half h = __float2half_rn(x);
    hp[off] = h;
    lp[off] = __float2half_rn(x - __half2float(h));
}

__global__ void k_rope16() {
    int t = blockIdx.x, hh = blockIdx.y, i = threadIdx.x;   // i 0..63
    float c = g_cos[t * 64 + i], s = g_sin[t * 64 + i];
    if (hh < NHQ) {
        const float* base = g_qkv + (size_t)t * QKVO + hh * HDIM;
        float x1 = base[i], x2 = base[64 + i];
        size_t o = ((size_t)hh * TT + t) * HDIM;
        w_split(g_qh, g_ql, o + i,      x1 * c - x2 * s);
        w_split(g_qh, g_ql, o + 64 + i, x2 * c + x1 * s);
    } else {
        int kvh = hh - NHQ;
        const float* base = g_qkv + (size_t)t * QKVO + (NHQ + kvh) * HDIM;
        float x1 = base[i], x2 = base[64 + i];
        size_t o = ((size_t)kvh * TT + t) * HDIM;
        w_split(g_kh, g_kl, o + i,      x1 * c - x2 * s);
        w_split(g_kh, g_kl, o + 64 + i, x2 * c + x1 * s);
    }
}

// ---------------- V fp16 split ----------------
__global__ void k_conv_v16() {
    int t = blockIdx.x, tid = threadIdx.x;   // 256 threads, 1024 elems
    const float* base = g_qkv + (size_t)t * QKVO + (NHQ + NKVH) * HDIM;
    for (int v = tid; v < NKVH * HDIM; v += 256) {
        int kvh = v >> 7, d = v & 127;
        float x = base[kvh * HDIM + d];
        w_split(g_vh, g_vl, ((size_t)kvh * TT + t) * HDIM + d, x);
    }
}

// ======================================================================
// fp16 flash attention v5: BM=128/BN=64, pre-split fp16 inputs,
// cp.async double-buffered K/V stages, Q fragments hoisted to regs.
// ======================================================================
#define FS 136
#define QSZB (128 * FS * 2)            // 34816 B per Q array
#define KSZB (64 * FS * 2)             // 17408 B per K/V array
#define STGB (4 * KSZB)                // 69632 B per stage (Kh,Kl,Vh,Vl)
#define FLASH_SMEM5 (2 * QSZB + 2 * STGB)   // 208896 B

__device__ __forceinline__ void ldsm4t(uint32_t& r0, uint32_t& r1, uint32_t& r2, uint32_t& r3, uint32_t a) {
    asm volatile("ldmatrix.sync.aligned.m8n8.x4.trans.shared.b16 {%0,%1,%2,%3},[%4];\n"
                 : "=r"(r0), "=r"(r1), "=r"(r2), "=r"(r3) : "r"(a));
}
__device__ __forceinline__ void mmaf16(float* c, const uint32_t* a, uint32_t b0, uint32_t b1) {
    asm volatile("mma.sync.aligned.m16n8k16.row.col.f32.f16.f16.f32 "
                 "{%0,%1,%2,%3},{%4,%5,%6,%7},{%8,%9},{%0,%1,%2,%3};\n"
                 : "+f"(c[0]), "+f"(c[1]), "+f"(c[2]), "+f"(c[3])
                 : "r"(a[0]), "r"(a[1]), "r"(a[2]), "r"(a[3]), "r"(b0), "r"(b1));
}
__device__ __forceinline__ uint32_t ph2(__half a, __half b) {
    return (uint32_t)__half_as_ushort(a) | ((uint32_t)__half_as_ushort(b) << 16);
}
__device__ __forceinline__ void splitp(float x, float y, uint32_t& hi, uint32_t& lo) {
    __half a = __float2half_rn(x), b = __float2half_rn(y);
    hi = ph2(a, b);
    lo = ph2(__float2half_rn(x - __half2float(a)), __float2half_rn(y - __half2float(b)));
}

__global__ __launch_bounds__(256) void k_flash5() {
    extern __shared__ char fsm[];
    const uint32_t SMB = s2u(fsm);

    const int tid = threadIdx.x;
    const int w = tid >> 5, lane = tid & 31;
    const int g = lane >> 2, tq = lane & 3;
    const int head = blockIdx.y, kvh = head >> 2;
    const int qb = (int)(gridDim.x - 1 - blockIdx.x);   // long tasks first
    const int q0 = qb * 128;

    const int l7 = lane & 7, sel = lane >> 3;
    const uint32_t dQ = ((16 * w + (sel & 1) * 8 + l7) * FS + (sel >> 1) * 8) * 2;
    const uint32_t dK = (((sel >> 1) * 8 + l7) * FS + (sel & 1) * 8) * 2;
    const uint32_t dV = 2 * KSZB + (((sel & 1) * 8 + l7) * FS + (sel >> 1) * 8) * 2;

    const int lr = tid >> 4, lch = tid & 15;   // loader: but use flat idx loops below

    // ---- prologue: Q (hi+lo) and K/V stage 0 via cp.async
    for (int v = tid; v < 2048; v += 256) {
        int r = v >> 4, ch = v & 15;
        size_t so = ((size_t)head * TT + q0 + r) * HDIM + ch * 8;
        uint32_t dst = SMB + (r * FS + ch * 8) * 2;
        CP16(dst, g_qh + so);
        CP16(dst + QSZB, g_ql + so);
    }
    {
        uint32_t stg = SMB + 2 * QSZB;
        for (int v = tid; v < 1024; v += 256) {
            int r = v >> 4, ch = v & 15;
            size_t so = ((size_t)kvh * TT + r) * HDIM + ch * 8;
            uint32_t drow = stg + (r * FS + ch * 8) * 2;
            CP16(drow,            g_kh + so);
            CP16(drow + KSZB,     g_kl + so);
            CP16(drow + 2 * KSZB, g_vh + so);
            CP16(drow + 3 * KSZB, g_vl + so);
        }
    }
    CPCOMMIT();
    CPWAIT0();
    __syncthreads();

    // ---- hoist Q fragments (tile-invariant)
    uint32_t qfh[8][4], qfl[8][4];
#pragma unroll
    for (int kt = 0; kt < 8; kt++) {
        ldsm4(qfh[kt][0], qfh[kt][1], qfh[kt][2], qfh[kt][3], SMB + dQ + 32 * kt);
        ldsm4(qfl[kt][0], qfl[kt][1], qfl[kt][2], qfl[kt][3], SMB + QSZB + dQ + 32 * kt);
    }

    float m0r = -INFINITY, m1r = -INFINITY, l0r = 0.f, l1r = 0.f;
    float O[16][4];
#pragma unroll
    for (int t = 0; t < 16; t++) { O[t][0]=0.f; O[t][1]=0.f; O[t][2]=0.f; O[t][3]=0.f; }

    const int rowg = q0 + 16 * w + g;
    const int nkb = 2 * qb + 2;

    for (int kb = 0; kb < nkb; kb++) {
        if (kb > 0) { CPWAIT0(); __syncthreads(); }
        if (kb + 1 < nkb) {
            int k1 = (kb + 1) * 64;
            uint32_t stg = SMB + 2 * QSZB + ((kb + 1) & 1) * STGB;
            for (int v = tid; v < 1024; v += 256) {
                int r = v >> 4, ch = v & 15;
                size_t so = ((size_t)kvh * TT + k1 + r) * HDIM + ch * 8;
                uint32_t drow = stg + (r * FS + ch * 8) * 2;
                CP16(drow,            g_kh + so);
                CP16(drow + KSZB,     g_kl + so);
                CP16(drow + 2 * KSZB, g_vh + so);
                CP16(drow + 3 * KSZB, g_vl + so);
            }
            CPCOMMIT();
        }
        const uint32_t stg = SMB + 2 * QSZB + (kb & 1) * STGB;
        const uint32_t aKh = stg + dK, aKl = aKh + KSZB;
        const uint32_t aVh = stg + dV, aVl = aVh + KSZB;
        const int k0 = kb * 64;

        // ---- S = Q K^T (split fp16)
        float sc[8][4];
#pragma unroll
        for (int j = 0; j < 8; j++) { sc[j][0]=0.f; sc[j][1]=0.f; sc[j][2]=0.f; sc[j][3]=0.f; }
#pragma unroll
        for (int kt = 0; kt < 8; kt++) {
            uint32_t kh[4], kl_[4];
#pragma unroll
            for (int p = 0; p < 4; p++) {
                ldsm4(kh[0], kh[1], kh[2], kh[3], aKh + 4352 * p + 32 * kt);
                ldsm4(kl_[0], kl_[1], kl_[2], kl_[3], aKl + 4352 * p + 32 * kt);
                mmaf16(sc[2 * p],     qfh[kt], kh[0], kh[1]);
                mmaf16(sc[2 * p],     qfh[kt], kl_[0], kl_[1]);
                mmaf16(sc[2 * p],     qfl[kt], kh[0], kh[1]);
                mmaf16(sc[2 * p + 1], qfh[kt], kh[2], kh[3]);
                mmaf16(sc[2 * p + 1], qfh[kt], kl_[2], kl_[3]);
                mmaf16(sc[2 * p + 1], qfl[kt], kh[2], kh[3]);
            }
        }

        // ---- scale + causal mask
        bool tail = (kb >= 2 * qb);
#pragma unroll
        for (int j = 0; j < 8; j++) {
            int cb = k0 + 8 * j + 2 * tq;
#pragma unroll
            for (int e = 0; e < 2; e++) {
                float v0 = sc[j][e] * SCALE_QK;
                float v1 = sc[j][2 + e] * SCALE_QK;
                if (tail) {
                    if (cb + e > rowg)     v0 = -INFINITY;
                    if (cb + e > rowg + 8) v1 = -INFINITY;
                }
                sc[j][e] = v0; sc[j][2 + e] = v1;
            }
        }

        // ---- online softmax (rows g, g+8; reduce over tq quad)
        float mx0 = -INFINITY, mx1 = -INFINITY;
#pragma unroll
        for (int j = 0; j < 8; j++) {
            mx0 = fmaxf(mx0, fmaxf(sc[j][0], sc[j][1]));
            mx1 = fmaxf(mx1, fmaxf(sc[j][2], sc[j][3]));
        }
        mx0 = fmaxf(mx0, __shfl_xor_sync(0xffffffffu, mx0, 1));
        mx0 = fmaxf(mx0, __shfl_xor_sync(0xffffffffu, mx0, 2));
        mx1 = fmaxf(mx1, __shfl_xor_sync(0xffffffffu, mx1, 1));
        mx1 = fmaxf(mx1, __shfl_xor_sync(0xffffffffu, mx1, 2));
        float mn0 = fmaxf(m0r, mx0), mn1 = fmaxf(m1r, mx1);
        float c0 = __expf(m0r - mn0), c1 = __expf(m1r - mn1);
        m0r = mn0; m1r = mn1;
        float s0 = 0.f, s1 = 0.f;
#pragma unroll
        for (int j = 0; j < 8; j++) {
            sc[j][0] = __expf(sc[j][0] - mn0) * 1024.0f;
            sc[j][1] = __expf(sc[j][1] - mn0) * 1024.0f;
            sc[j][2] = __expf(sc[j][2] - mn1) * 1024.0f;
            sc[j][3] = __expf(sc[j][3] - mn1) * 1024.0f;
            s0 += sc[j][0] + sc[j][1];
            s1 += sc[j][2] + sc[j][3];
        }
        s0 += __shfl_xor_sync(0xffffffffu, s0, 1);
        s0 += __shfl_xor_sync(0xffffffffu, s0, 2);
        s1 += __shfl_xor_sync(0xffffffffu, s1, 1);
        s1 += __shfl_xor_sync(0xffffffffu, s1, 2);
        l0r = l0r * c0 + s0;
        l1r = l1r * c1 + s1;
#pragma unroll
        for (int t = 0; t < 16; t++) { O[t][0] *= c0; O[t][1] *= c0; O[t][2] *= c1; O[t][3] *= c1; }

        // ---- PV: P C-frags remap directly onto A-frags
#pragma unroll
        for (int jj = 0; jj < 4; jj++) {
            uint32_t pa[4], pl[4];
            splitp(sc[2 * jj][0],     sc[2 * jj][1],     pa[0], pl[0]);
            splitp(sc[2 * jj][2],     sc[2 * jj][3],     pa[1], pl[1]);
            splitp(sc[2 * jj + 1][0], sc[2 * jj + 1][1], pa[2], pl[2]);
            splitp(sc[2 * jj + 1][2], sc[2 * jj + 1][3], pa[3], pl[3]);
#pragma unroll
            for (int q = 0; q < 8; q++) {
                uint32_t vh[4], vl_[4];
                ldsm4t(vh[0], vh[1], vh[2], vh[3], aVh + 4352 * jj + 32 * q);
                ldsm4t(vl_[0], vl_[1], vl_[2], vl_[3], aVl + 4352 * jj + 32 * q);
                mmaf16(O[2 * q],     pa, vh[0], vh[1]);
                mmaf16(O[2 * q],     pa, vl_[0], vl_[1]);
                mmaf16(O[2 * q],     pl, vh[0], vh[1]);
                mmaf16(O[2 * q + 1], pa, vh[2], vh[3]);
                mmaf16(O[2 * q + 1], pa, vl_[2], vl_[3]);
                mmaf16(O[2 * q + 1], pl, vh[2], vh[3]);
            }
        }
    }

    // ---- epilogue: O / l -> g_attn
#pragma unroll
    for (int t = 0; t < 16; t++) {
        int col = head * HDIM + 8 * t + 2 * tq;
        float2 u;
        u.x = O[t][0] / l0r;  u.y = O[t][1] / l0r;
        *(float2*)&g_attn[(size_t)rowg * HIDN + col] = u;
        u.x = O[t][2] / l1r;  u.y = O[t][3] / l1r;
        *(float2*)&g_attn[(size_t)(rowg + 8) * HIDN + col] = u;
    }
}

// ---------------- dynamic quant with sum (reciprocal hoisted) ----------------
__global__ __launch_bounds__(256) void k_quant() {
    __shared__ float xrow[HIDN];
    __shared__ float red[256];
    int t = blockIdx.x, tid = threadIdx.x;
    const float* src = g_attn + (size_t)t * HIDN;
    float amax = 0.f;
    for (int c = tid; c < HIDN; c += 256) { float x = src[c]; xrow[c] = x; amax = fmaxf(amax, fabsf(x)); }
    red[tid] = amax; __syncthreads();
    for (int k = 128; k > 0; k >>= 1) { if (tid < k) red[tid] = fmaxf(red[tid], red[tid + k]); __syncthreads(); }
    float s = fmaxf(red[0], 1e-8f) / 127.0f;
    float sinv = 1.0f / s;
    __nv_bfloat16* q = g_q2 + (size_t)t * HIDN;
    float qs = 0.f;
    for (int c = tid; c < HIDN; c += 256) {
        float v = rintf(xrow[c] * sinv);
        v = fminf(fmaxf(v, -127.f), 127.f);
        q[c] = __float2bfloat16(v);
        qs += v;
    }
    __syncthreads();
    red[tid] = qs; __syncthreads();
    for (int k = 128; k > 0; k >>= 1) { if (tid < k) red[tid] += red[tid + k]; __syncthreads(); }
    if (tid == 0) { g_s2[t] = s; g_sum2[t] = red[0]; }
}

// ---------------- launch ----------------
extern "C" void kernel_launch(void* const* d_in, const int* in_sizes, int n_in,
                              void* d_out, int out_size) {
    const int*   positions   = (const int*)d_in[0];
    const int*   q_act       = (const int*)d_in[1];
    const float* act_scale   = (const float*)d_in[2];
    const int*   w_qkv_q     = (const int*)d_in[3];
    const float* w_qkv_scale = (const float*)d_in[4];
    const float* w_qkv_zero  = (const float*)d_in[5];
    const int*   w_o_q       = (const int*)d_in[6];
    const float* w_o_scale   = (const float*)d_in[7];
    const float* w_o_zero    = (const float*)d_in[8];
    float* out = (float*)d_out;

    __nv_bfloat16 *A, *Wqkv, *Wo, *q2;
    float *asum, *qkv, *s2, *sum2;
    cudaGetSymbolAddress((void**)&A,    g_A);
    cudaGetSymbolAddress((void**)&Wqkv, g_Wqkv);
    cudaGetSymbolAddress((void**)&Wo,   g_Wo);
    cudaGetSymbolAddress((void**)&q2,   g_q2);
    cudaGetSymbolAddress((void**)&asum, g_asum);
    cudaGetSymbolAddress((void**)&qkv,  g_qkv);
    cudaGetSymbolAddress((void**)&s2,   g_s2);
    cudaGetSymbolAddress((void**)&sum2, g_sum2);

    cudaFuncSetAttribute(k_flash5, cudaFuncAttributeMaxDynamicSharedMemorySize, FLASH_SMEM5);
    cudaFuncSetAttribute(k_gemm,   cudaFuncAttributeMaxDynamicSharedMemorySize, GEMM_SMEM);

    k_rope_tab<<<TT, 64>>>(positions);
    k_prep_a<<<TT, 256>>>(q_act);
    k_conv_w<<<2048, 256>>>(w_qkv_q, Wqkv, QKVO * HIDN);

    dim3 g1(QKVO / 128, TT / 256);
    k_gemm<<<g1, 256, GEMM_SMEM>>>(A, Wqkv, qkv, TT, QKVO, HIDN, act_scale, asum, w_qkv_scale, w_qkv_zero);

    dim3 g2(TT, NHQ + NKVH);
    k_rope16<<<g2, 64>>>();
    k_conv_v16<<<TT, 256>>>();

    dim3 g3(TT / 128, NHQ);
    k_flash5<<<g3, 256, FLASH_SMEM5>>>();

    k_quant<<<TT, 256>>>();

    k_conv_w<<<2048, 256>>>(w_o_q, Wo, HIDN * HIDN);

    dim3 g4(HIDN / 128, TT / 256);
    k_gemm<<<g4, 256, GEMM_SMEM>>>(q2, Wo, out, TT, HIDN, HIDN, s2, sum2, w_o_scale, w_o_zero);
}

// round 16
// speedup vs baseline: 1.1502x; 1.0008x over previous
#include <cuda_runtime.h>
#include <cuda_bf16.h>
#include <cuda_fp16.h>
#include <math.h>
#include <float.h>
#include <stdint.h>

#define TT 2048
#define HIDN 4096
#define NHQ 32
#define NKVH 8
#define HDIM 128
#define QKVO 6144
#define SCALE_QK 0.08838834764831845f

// ---------------- device scratch (static; no cudaMalloc) ----------------
static __device__ __nv_bfloat16 g_A[(size_t)TT * HIDN];
static __device__ float         g_asum[TT];
static __device__ __nv_bfloat16 g_Wqkv[(size_t)QKVO * HIDN];
static __device__ __nv_bfloat16 g_Wo[(size_t)HIDN * HIDN];
static __device__ float         g_qkv[(size_t)TT * QKVO];
static __device__ __half        g_qh[(size_t)NHQ * TT * HDIM];   // Q hi  [h][t][d]
static __device__ __half        g_ql[(size_t)NHQ * TT * HDIM];   // Q lo
static __device__ __half        g_kh[(size_t)NKVH * TT * HDIM];  // K hi  [kvh][t][d]
static __device__ __half        g_kl[(size_t)NKVH * TT * HDIM];
static __device__ __half        g_vh[(size_t)NKVH * TT * HDIM];  // V hi
static __device__ __half        g_vl[(size_t)NKVH * TT * HDIM];
static __device__ float         g_attn[(size_t)TT * HIDN];
static __device__ __nv_bfloat16 g_q2[(size_t)TT * HIDN];
static __device__ float         g_s2[TT];
static __device__ float         g_sum2[TT];
static __device__ float         g_cos[TT * 64];
static __device__ float         g_sin[TT * 64];

__device__ __forceinline__ uint32_t s2u(const void* p) { return (uint32_t)__cvta_generic_to_shared(p); }

// ---------------- RoPE table (fp64 inner) ----------------
__global__ void k_rope_tab(const int* __restrict__ pos) {
    int t = blockIdx.x, i = threadIdx.x;               // i: 0..63
    float ef = (float)(2 * i) / 128.0f;
    float invf = (float)(1.0 / pow(10000.0, (double)ef));
    float fr = (float)pos[t] * invf;                   // fp32 mul = reference rounding
    g_cos[t * 64 + i] = (float)cos((double)fr);
    g_sin[t * 64 + i] = (float)sin((double)fr);
}

// ---------------- activation prep ----------------
__global__ void k_prep_a(const int* __restrict__ qa) {
    int t = blockIdx.x, tid = threadIdx.x;
    const int* row = qa + (size_t)t * HIDN;
    __nv_bfloat16* arow = g_A + (size_t)t * HIDN;
    int s = 0;
    for (int c = tid; c < HIDN; c += 256) { int v = row[c]; s += v; arow[c] = __float2bfloat16((float)v); }
    __shared__ int red[256];
    red[tid] = s; __syncthreads();
    for (int k = 128; k > 0; k >>= 1) { if (tid < k) red[tid] += red[tid + k]; __syncthreads(); }
    if (tid == 0) g_asum[t] = (float)red[0];
}

__global__ void k_conv_w(const int* __restrict__ w, __nv_bfloat16* __restrict__ o, int n) {
    int i = blockIdx.x * blockDim.x + threadIdx.x;
    int stride = gridDim.x * blockDim.x;
    for (int v = i; v < n / 4; v += stride) {
        int4 x = ((const int4*)w)[v];
        __nv_bfloat162 p0 = {__float2bfloat16((float)x.x), __float2bfloat16((float)x.y)};
        __nv_bfloat162 p1 = {__float2bfloat16((float)x.z), __float2bfloat16((float)x.w)};
        ((__nv_bfloat162*)o)[2 * v] = p0;
        ((__nv_bfloat162*)o)[2 * v + 1] = p1;
    }
}

// ==================================================================
// bf16 HMMA GEMM v3.1: CTA 256x128, warp 64x64, 4-stage cp.async
// pipeline, ldmatrix fragments, fused W4A8 epilogue. Bit-exact.
// ==================================================================
#define GST 40
#define ASTG (256 * GST)
#define BSTG (128 * GST)
#define GEMM_SMEM (4 * (ASTG + BSTG) * 2)   // 122880 B

__device__ __forceinline__ void ldsm4(uint32_t& r0, uint32_t& r1, uint32_t& r2, uint32_t& r3, uint32_t a) {
    asm volatile("ldmatrix.sync.aligned.m8n8.x4.shared.b16 {%0,%1,%2,%3},[%4];\n"
                 : "=r"(r0), "=r"(r1), "=r"(r2), "=r"(r3) : "r"(a));
}
__device__ __forceinline__ void mmabf(float* c, const uint32_t* a, uint32_t b0, uint32_t b1) {
    asm volatile("mma.sync.aligned.m16n8k16.row.col.f32.bf16.bf16.f32 "
                 "{%0,%1,%2,%3},{%4,%5,%6,%7},{%8,%9},{%0,%1,%2,%3};\n"
                 : "+f"(c[0]), "+f"(c[1]), "+f"(c[2]), "+f"(c[3])
                 : "r"(a[0]), "r"(a[1]), "r"(a[2]), "r"(a[3]), "r"(b0), "r"(b1));
}
#define CP16(dst, src) asm volatile("cp.async.cg.shared.global [%0], [%1], 16;\n" :: "r"(dst), "l"(src))
#define CPCOMMIT()     asm volatile("cp.async.commit_group;\n")
#define CPWAIT2()      asm volatile("cp.async.wait_group 2;\n" ::: "memory")
#define CPWAIT0()      asm volatile("cp.async.wait_group 0;\n" ::: "memory")

__global__ __launch_bounds__(256, 1) void k_gemm(
    const __nv_bfloat16* __restrict__ A, const __nv_bfloat16* __restrict__ B,
    float* __restrict__ C, int M, int N, int K,
    const float* __restrict__ rs, const float* __restrict__ rsum,
    const float* __restrict__ cs, const float* __restrict__ cz)
{
    extern __shared__ __nv_bfloat16 gsm[];
    __nv_bfloat16* Ash = gsm;
    __nv_bfloat16* Bsh = gsm + 4 * ASTG;

    const int tid = threadIdx.x;
    const int warp = tid >> 5, lane = tid & 31;
    const int wm = warp >> 1, wn = warp & 1;
    const int g = lane >> 2, tq = lane & 3;
    const int sel = lane >> 3, l7 = lane & 7;
    const int bm0 = blockIdx.y * 256, bn0 = blockIdx.x * 128;

    const int r0 = tid >> 2, c0 = (tid & 3) * 8;
    const __nv_bfloat16* Abase = A + (size_t)(bm0 + r0) * K + c0;
    const __nv_bfloat16* Bbase = B + (size_t)(bn0 + r0) * K + c0;
    const size_t rowK64 = (size_t)64 * K;

    uint32_t sA = s2u(Ash), sB = s2u(Bsh);
    uint32_t dA = sA + (r0 * GST + c0) * 2;
    uint32_t dB = sB + (r0 * GST + c0) * 2;

    uint32_t aA = sA + ((wm * 64 + (sel & 1) * 8 + l7) * GST + (sel >> 1) * 8) * 2;
    uint32_t aB = sB + ((wn * 64 + (sel >> 1) * 8 + l7) * GST + (sel & 1) * 8) * 2;

    float acc[4][8][4];
#pragma unroll
    for (int i = 0; i < 4; i++)
#pragma unroll
        for (int j = 0; j < 8; j++) { acc[i][j][0]=0.f; acc[i][j][1]=0.f; acc[i][j][2]=0.f; acc[i][j][3]=0.f; }

    const int KT = K >> 5;

#pragma unroll
    for (int s = 0; s < 3; s++) {
        const __nv_bfloat16* Ak = Abase + s * 32;
        const __nv_bfloat16* Bk = Bbase + s * 32;
        uint32_t oA = dA + s * ASTG * 2, oB = dB + s * BSTG * 2;
#pragma unroll
        for (int q = 0; q < 4; q++) CP16(oA + q * 64 * GST * 2, Ak + q * rowK64);
#pragma unroll
        for (int q = 0; q < 2; q++) CP16(oB + q * 64 * GST * 2, Bk + q * rowK64);
        CPCOMMIT();
    }
    CPWAIT2();          // stage 0 resident
    __syncthreads();

    for (int kb = 0; kb < KT; kb++) {
        const int st = kb & 3;
        if (kb + 3 < KT) {
            const int ns = (kb + 3) & 3;   // = (kb-1)&3: readers done last iter, barrier-protected
            const __nv_bfloat16* Ak = Abase + (kb + 3) * 32;
            const __nv_bfloat16* Bk = Bbase + (kb + 3) * 32;
            uint32_t oA = dA + ns * ASTG * 2, oB = dB + ns * BSTG * 2;
#pragma unroll
            for (int q = 0; q < 4; q++) CP16(oA + q * 64 * GST * 2, Ak + q * rowK64);
#pragma unroll
            for (int q = 0; q < 2; q++) CP16(oB + q * 64 * GST * 2, Bk + q * rowK64);
            CPCOMMIT();
        }
        const uint32_t stA = aA + st * ASTG * 2;
        const uint32_t stB = aB + st * BSTG * 2;
#pragma unroll
        for (int ks = 0; ks < 2; ks++) {
            uint32_t af[4][4], bf[4][4];
#pragma unroll
            for (int mi = 0; mi < 4; mi++)
                ldsm4(af[mi][0], af[mi][1], af[mi][2], af[mi][3], stA + mi * 16 * GST * 2 + ks * 32);
#pragma unroll
            for (int p = 0; p < 4; p++)
                ldsm4(bf[p][0], bf[p][1], bf[p][2], bf[p][3], stB + p * 16 * GST * 2 + ks * 32);
#pragma unroll
            for (int mi = 0; mi < 4; mi++)
#pragma unroll
                for (int p = 0; p < 4; p++) {
                    mmabf(acc[mi][2 * p],     af[mi], bf[p][0], bf[p][1]);
                    mmabf(acc[mi][2 * p + 1], af[mi], bf[p][2], bf[p][3]);
                }
        }
        if (kb + 1 < KT) {
            CPWAIT2();          // next stage resident (<=2 groups outstanding)
            __syncthreads();
        }
    }

#pragma unroll
    for (int mi = 0; mi < 4; mi++) {
        int rA = bm0 + wm * 64 + mi * 16 + g;
        int rB = rA + 8;
        float rsA = rs[rA], rmA = rsum[rA];
        float rsB = rs[rB], rmB = rsum[rB];
#pragma unroll
        for (int ni = 0; ni < 8; ni++) {
            int col = bn0 + wn * 64 + ni * 8 + 2 * tq;
            float cs0 = cs[col], cs1 = cs[col + 1];
            float cz0 = cz[col], cz1 = cz[col + 1];
            float2 o0, o1;
            o0.x = (rsA * cs0) * (acc[mi][ni][0] - cz0 * rmA);
            o0.y = (rsA * cs1) * (acc[mi][ni][1] - cz1 * rmA);
            o1.x = (rsB * cs0) * (acc[mi][ni][2] - cz0 * rmB);
            o1.y = (rsB * cs1) * (acc[mi][ni][3] - cz1 * rmB);
            *(float2*)&C[(size_t)rA * N + col] = o0;
            *(float2*)&C[(size_t)rB * N + col] = o1;
        }
    }
}

// ---------------- fused RoPE+split (Q,K) and split (V) ----------------
__device__ __forceinline__ void w_split(__half* hp, __half* lp, size_t off, float x) {
    __half h = __float2half_rn(x);
    hp[off] = h;
    lp[off] = __float2half_rn(x - __half2float(h));
}

__global__ __launch_bounds__(256) void k_split16() {
    int t = blockIdx.x, tid = threadIdx.x;
    const float* row = g_qkv + (size_t)t * QKVO;
    // rope: 40 head-slots (32 Q + 8 K) x 64 lanes
    for (int v = tid; v < (NHQ + NKVH) * 64; v += 256) {
        int hh = v >> 6, i = v & 63;
        float c = g_cos[t * 64 + i], s = g_sin[t * 64 + i];
        const float* base = row + hh * HDIM;
        float x1 = base[i], x2 = base[64 + i];
        float r1 = x1 * c - x2 * s, r2 = x2 * c + x1 * s;
        if (hh < NHQ) {
            size_t o = ((size_t)hh * TT + t) * HDIM;
            w_split(g_qh, g_ql, o + i, r1);
            w_split(g_qh, g_ql, o + 64 + i, r2);
        } else {
            size_t o = ((size_t)(hh - NHQ) * TT + t) * HDIM;
            w_split(g_kh, g_kl, o + i, r1);
            w_split(g_kh, g_kl, o + 64 + i, r2);
        }
    }
    // V split: 8 kvh x 128
    const float* vbase = row + (NHQ + NKVH) * HDIM;
    for (int v = tid; v < NKVH * HDIM; v += 256) {
        int kvh = v >> 7, d = v & 127;
        w_split(g_vh, g_vl, ((size_t)kvh * TT + t) * HDIM + d, vbase[kvh * HDIM + d]);
    }
}

// ======================================================================
// fp16 flash attention v5 (unchanged from R15): BM=128/BN=64,
// pre-split fp16 inputs, cp.async double-buffered K/V, Q frags in regs.
// ======================================================================
#define FS 136
#define QSZB (128 * FS * 2)
#define KSZB (64 * FS * 2)
#define STGB (4 * KSZB)
#define FLASH_SMEM5 (2 * QSZB + 2 * STGB)

__device__ __forceinline__ void ldsm4t(uint32_t& r0, uint32_t& r1, uint32_t& r2, uint32_t& r3, uint32_t a) {
    asm volatile("ldmatrix.sync.aligned.m8n8.x4.trans.shared.b16 {%0,%1,%2,%3},[%4];\n"
                 : "=r"(r0), "=r"(r1), "=r"(r2), "=r"(r3) : "r"(a));
}
__device__ __forceinline__ void mmaf16(float* c, const uint32_t* a, uint32_t b0, uint32_t b1) {
    asm volatile("mma.sync.aligned.m16n8k16.row.col.f32.f16.f16.f32 "
                 "{%0,%1,%2,%3},{%4,%5,%6,%7},{%8,%9},{%0,%1,%2,%3};\n"
                 : "+f"(c[0]), "+f"(c[1]), "+f"(c[2]), "+f"(c[3])
                 : "r"(a[0]), "r"(a[1]), "r"(a[2]), "r"(a[3]), "r"(b0), "r"(b1));
}
__device__ __forceinline__ uint32_t ph2(__half a, __half b) {
    return (uint32_t)__half_as_ushort(a) | ((uint32_t)__half_as_ushort(b) << 16);
}
__device__ __forceinline__ void splitp(float x, float y, uint32_t& hi, uint32_t& lo) {
    __half a = __float2half_rn(x), b = __float2half_rn(y);
    hi = ph2(a, b);
    lo = ph2(__float2half_rn(x - __half2float(a)), __float2half_rn(y - __half2float(b)));
}

__global__ __launch_bounds__(256) void k_flash5() {
    extern __shared__ char fsm[];
    const uint32_t SMB = s2u(fsm);

    const int tid = threadIdx.x;
    const int w = tid >> 5, lane = tid & 31;
    const int g = lane >> 2, tq = lane & 3;
    const int head = blockIdx.y, kvh = head >> 2;
    const int qb = (int)(gridDim.x - 1 - blockIdx.x);
    const int q0 = qb * 128;

    const int l7 = lane & 7, sel = lane >> 3;
    const uint32_t dQ = ((16 * w + (sel & 1) * 8 + l7) * FS + (sel >> 1) * 8) * 2;
    const uint32_t dK = (((sel >> 1) * 8 + l7) * FS + (sel & 1) * 8) * 2;
    const uint32_t dV = 2 * KSZB + (((sel & 1) * 8 + l7) * FS + (sel >> 1) * 8) * 2;

    for (int v = tid; v < 2048; v += 256) {
        int r = v >> 4, ch = v & 15;
        size_t so = ((size_t)head * TT + q0 + r) * HDIM + ch * 8;
        uint32_t dst = SMB + (r * FS + ch * 8) * 2;
        CP16(dst, g_qh + so);
        CP16(dst + QSZB, g_ql + so);
    }
    {
        uint32_t stg = SMB + 2 * QSZB;
        for (int v = tid; v < 1024; v += 256) {
            int r = v >> 4, ch = v & 15;
            size_t so = ((size_t)kvh * TT + r) * HDIM + ch * 8;
            uint32_t drow = stg + (r * FS + ch * 8) * 2;
            CP16(drow,            g_kh + so);
            CP16(drow + KSZB,     g_kl + so);
            CP16(drow + 2 * KSZB, g_vh + so);
            CP16(drow + 3 * KSZB, g_vl + so);
        }
    }
    CPCOMMIT();
    CPWAIT0();
    __syncthreads();

    uint32_t qfh[8][4], qfl[8][4];
#pragma unroll
    for (int kt = 0; kt < 8; kt++) {
        ldsm4(qfh[kt][0], qfh[kt][1], qfh[kt][2], qfh[kt][3], SMB + dQ + 32 * kt);
        ldsm4(qfl[kt][0], qfl[kt][1], qfl[kt][2], qfl[kt][3], SMB + QSZB + dQ + 32 * kt);
    }

    float m0r = -INFINITY, m1r = -INFINITY, l0r = 0.f, l1r = 0.f;
    float O[16][4];
#pragma unroll
    for (int t = 0; t < 16; t++) { O[t][0]=0.f; O[t][1]=0.f; O[t][2]=0.f; O[t][3]=0.f; }

    const int rowg = q0 + 16 * w + g;
    const int nkb = 2 * qb + 2;

    for (int kb = 0; kb < nkb; kb++) {
        if (kb > 0) { CPWAIT0(); __syncthreads(); }
        if (kb + 1 < nkb) {
            int k1 = (kb + 1) * 64;
            uint32_t stg = SMB + 2 * QSZB + ((kb + 1) & 1) * STGB;
            for (int v = tid; v < 1024; v += 256) {
                int r = v >> 4, ch = v & 15;
                size_t so = ((size_t)kvh * TT + k1 + r) * HDIM + ch * 8;
                uint32_t drow = stg + (r * FS + ch * 8) * 2;
                CP16(drow,            g_kh + so);
                CP16(drow + KSZB,     g_kl + so);
                CP16(drow + 2 * KSZB, g_vh + so);
                CP16(drow + 3 * KSZB, g_vl + so);
            }
            CPCOMMIT();
        }
        const uint32_t stg = SMB + 2 * QSZB + (kb & 1) * STGB;
        const uint32_t aKh = stg + dK, aKl = aKh + KSZB;
        const uint32_t aVh = stg + dV, aVl = aVh + KSZB;
        const int k0 = kb * 64;

        float sc[8][4];
#pragma unroll
        for (int j = 0; j < 8; j++) { sc[j][0]=0.f; sc[j][1]=0.f; sc[j][2]=0.f; sc[j][3]=0.f; }
#pragma unroll
        for (int kt = 0; kt < 8; kt++) {
            uint32_t kh[4], kl_[4];
#pragma unroll
            for (int p = 0; p < 4; p++) {
                ldsm4(kh[0], kh[1], kh[2], kh[3], aKh + 4352 * p + 32 * kt);
                ldsm4(kl_[0], kl_[1], kl_[2], kl_[3], aKl + 4352 * p + 32 * kt);
                mmaf16(sc[2 * p],     qfh[kt], kh[0], kh[1]);
                mmaf16(sc[2 * p],     qfh[kt], kl_[0], kl_[1]);
                mmaf16(sc[2 * p],     qfl[kt], kh[0], kh[1]);
                mmaf16(sc[2 * p + 1], qfh[kt], kh[2], kh[3]);
                mmaf16(sc[2 * p + 1], qfh[kt], kl_[2], kl_[3]);
                mmaf16(sc[2 * p + 1], qfl[kt], kh[2], kh[3]);
            }
        }

        bool tail = (kb >= 2 * qb);
#pragma unroll
        for (int j = 0; j < 8; j++) {
            int cb = k0 + 8 * j + 2 * tq;
#pragma unroll
            for (int e = 0; e < 2; e++) {
                float v0 = sc[j][e] * SCALE_QK;
                float v1 = sc[j][2 + e] * SCALE_QK;
                if (tail) {
                    if (cb + e > rowg)     v0 = -INFINITY;
                    if (cb + e > rowg + 8) v1 = -INFINITY;
                }
                sc[j][e] = v0; sc[j][2 + e] = v1;
            }
        }

        float mx0 = -INFINITY, mx1 = -INFINITY;
#pragma unroll
        for (int j = 0; j < 8; j++) {
            mx0 = fmaxf(mx0, fmaxf(sc[j][0], sc[j][1]));
            mx1 = fmaxf(mx1, fmaxf(sc[j][2], sc[j][3]));
        }
        mx0 = fmaxf(mx0, __shfl_xor_sync(0xffffffffu, mx0, 1));
        mx0 = fmaxf(mx0, __shfl_xor_sync(0xffffffffu, mx0, 2));
        mx1 = fmaxf(mx1, __shfl_xor_sync(0xffffffffu, mx1, 1));
        mx1 = fmaxf(mx1, __shfl_xor_sync(0xffffffffu, mx1, 2));
        float mn0 = fmaxf(m0r, mx0), mn1 = fmaxf(m1r, mx1);
        float c0 = __expf(m0r - mn0), c1 = __expf(m1r - mn1);
        m0r = mn0; m1r = mn1;
        float s0 = 0.f, s1 = 0.f;
#pragma unroll
        for (int j = 0; j < 8; j++) {
            sc[j][0] = __expf(sc[j][0] - mn0) * 1024.0f;
            sc[j][1] = __expf(sc[j][1] - mn0) * 1024.0f;
            sc[j][2] = __expf(sc[j][2] - mn1) * 1024.0f;
            sc[j][3] = __expf(sc[j][3] - mn1) * 1024.0f;
            s0 += sc[j][0] + sc[j][1];
            s1 += sc[j][2] + sc[j][3];
        }
        s0 += __shfl_xor_sync(0xffffffffu, s0, 1);
        s0 += __shfl_xor_sync(0xffffffffu, s0, 2);
        s1 += __shfl_xor_sync(0xffffffffu, s1, 1);
        s1 += __shfl_xor_sync(0xffffffffu, s1, 2);
        l0r = l0r * c0 + s0;
        l1r = l1r * c1 + s1;
#pragma unroll
        for (int t = 0; t < 16; t++) { O[t][0] *= c0; O[t][1] *= c0; O[t][2] *= c1; O[t][3] *= c1; }

#pragma unroll
        for (int jj = 0; jj < 4; jj++) {
            uint32_t pa[4], pl[4];
            splitp(sc[2 * jj][0],     sc[2 * jj][1],     pa[0], pl[0]);
            splitp(sc[2 * jj][2],     sc[2 * jj][3],     pa[1], pl[1]);
            splitp(sc[2 * jj + 1][0], sc[2 * jj + 1][1], pa[2], pl[2]);
            splitp(sc[2 * jj + 1][2], sc[2 * jj + 1][3], pa[3], pl[3]);
#pragma unroll
            for (int q = 0; q < 8; q++) {
                uint32_t vh[4], vl_[4];
                ldsm4t(vh[0], vh[1], vh[2], vh[3], aVh + 4352 * jj + 32 * q);
                ldsm4t(vl_[0], vl_[1], vl_[2], vl_[3], aVl + 4352 * jj + 32 * q);
                mmaf16(O[2 * q],     pa, vh[0], vh[1]);
                mmaf16(O[2 * q],     pa, vl_[0], vl_[1]);
                mmaf16(O[2 * q],     pl, vh[0], vh[1]);
                mmaf16(O[2 * q + 1], pa, vh[2], vh[3]);
                mmaf16(O[2 * q + 1], pa, vl_[2], vl_[3]);
                mmaf16(O[2 * q + 1], pl, vh[2], vh[3]);
            }
        }
    }

#pragma unroll
    for (int t = 0; t < 16; t++) {
        int col = head * HDIM + 8 * t + 2 * tq;
        float2 u;
        u.x = O[t][0] / l0r;  u.y = O[t][1] / l0r;
        *(float2*)&g_attn[(size_t)rowg * HIDN + col] = u;
        u.x = O[t][2] / l1r;  u.y = O[t][3] / l1r;
        *(float2*)&g_attn[(size_t)(rowg + 8) * HIDN + col] = u;
    }
}

// ---------------- dynamic quant with sum (reciprocal hoisted) ----------------
__global__ __launch_bounds__(256) void k_quant() {
    __shared__ float xrow[HIDN];
    __shared__ float red[256];
    int t = blockIdx.x, tid = threadIdx.x;
    const float* src = g_attn + (size_t)t * HIDN;
    float amax = 0.f;
    for (int c = tid; c < HIDN; c += 256) { float x = src[c]; xrow[c] = x; amax = fmaxf(amax, fabsf(x)); }
    red[tid] = amax; __syncthreads();
    for (int k = 128; k > 0; k >>= 1) { if (tid < k) red[tid] = fmaxf(red[tid], red[tid + k]); __syncthreads(); }
    float s = fmaxf(red[0], 1e-8f) / 127.0f;
    float sinv = 1.0f / s;
    __nv_bfloat16* q = g_q2 + (size_t)t * HIDN;
    float qs = 0.f;
    for (int c = tid; c < HIDN; c += 256) {
        float v = rintf(xrow[c] * sinv);
        v = fminf(fmaxf(v, -127.f), 127.f);
        q[c] = __float2bfloat16(v);
        qs += v;
    }
    __syncthreads();
    red[tid] = qs; __syncthreads();
    for (int k = 128; k > 0; k >>= 1) { if (tid < k) red[tid] += red[tid + k]; __syncthreads(); }
    if (tid == 0) { g_s2[t] = s; g_sum2[t] = red[0]; }
}

// ---------------- launch ----------------
extern "C" void kernel_launch(void* const* d_in, const int* in_sizes, int n_in,
                              void* d_out, int out_size) {
    const int*   positions   = (const int*)d_in[0];
    const int*   q_act       = (const int*)d_in[1];
    const float* act_scale   = (const float*)d_in[2];
    const int*   w_qkv_q     = (const int*)d_in[3];
    const float* w_qkv_scale = (const float*)d_in[4];
    const float* w_qkv_zero  = (const float*)d_in[5];
    const int*   w_o_q       = (const int*)d_in[6];
    const float* w_o_scale   = (const float*)d_in[7];
    const float* w_o_zero    = (const float*)d_in[8];
    float* out = (float*)d_out;

    __nv_bfloat16 *A, *Wqkv, *Wo, *q2;
    float *asum, *qkv, *s2, *sum2;
    cudaGetSymbolAddress((void**)&A,    g_A);
    cudaGetSymbolAddress((void**)&Wqkv, g_Wqkv);
    cudaGetSymbolAddress((void**)&Wo,   g_Wo);
    cudaGetSymbolAddress((void**)&q2,   g_q2);
    cudaGetSymbolAddress((void**)&asum, g_asum);
    cudaGetSymbolAddress((void**)&qkv,  g_qkv);
    cudaGetSymbolAddress((void**)&s2,   g_s2);
    cudaGetSymbolAddress((void**)&sum2, g_sum2);

    cudaFuncSetAttribute(k_flash5, cudaFuncAttributeMaxDynamicSharedMemorySize, FLASH_SMEM5);
    cudaFuncSetAttribute(k_gemm,   cudaFuncAttributeMaxDynamicSharedMemorySize, GEMM_SMEM);

    k_rope_tab<<<TT, 64>>>(positions);
    k_prep_a<<<TT, 256>>>(q_act);
    k_conv_w<<<2048, 256>>>(w_qkv_q, Wqkv, QKVO * HIDN);

    dim3 g1(QKVO / 128, TT / 256);
    k_gemm<<<g1, 256, GEMM_SMEM>>>(A, Wqkv, qkv, TT, QKVO, HIDN, act_scale, asum, w_qkv_scale, w_qkv_zero);

    k_split16<<<TT, 256>>>();

    dim3 g3(TT / 128, NHQ);
    k_flash5<<<g3, 256, FLASH_SMEM5>>>();

    k_quant<<<TT, 256>>>();

    k_conv_w<<<2048, 256>>>(w_o_q, Wo, HIDN * HIDN);

    dim3 g4(HIDN / 128, TT / 256);
    k_gemm<<<g4, 256, GEMM_SMEM>>>(q2, Wo, out, TT, HIDN, HIDN, s2, sum2, w_o_scale, w_o_zero);
}

// round 17
// speedup vs baseline: 1.1798x; 1.0258x over previous
#include <cuda_runtime.h>
#include <cuda_bf16.h>
#include <cuda_fp16.h>
#include <math.h>
#include <float.h>
#include <stdint.h>

#define TT 2048
#define HIDN 4096
#define NHQ 32
#define NKVH 8
#define HDIM 128
#define QKVO 6144
#define SCALE_QK 0.08838834764831845f

// ---------------- device scratch (static; no cudaMalloc) ----------------
static __device__ __nv_bfloat16 g_A[(size_t)TT * HIDN];
static __device__ float         g_asum[TT];
static __device__ __nv_bfloat16 g_Wqkv[(size_t)QKVO * HIDN];
static __device__ __nv_bfloat16 g_Wo[(size_t)HIDN * HIDN];
static __device__ float         g_qkv[(size_t)TT * QKVO];
static __device__ __half        g_qh[(size_t)NHQ * TT * HDIM];   // Q hi  [h][t][d]
static __device__ __half        g_ql[(size_t)NHQ * TT * HDIM];   // Q lo
static __device__ __half        g_kh[(size_t)NKVH * TT * HDIM];  // K hi  [kvh][t][d]
static __device__ __half        g_kl[(size_t)NKVH * TT * HDIM];
static __device__ __half        g_vh[(size_t)NKVH * TT * HDIM];  // V hi
static __device__ __half        g_vl[(size_t)NKVH * TT * HDIM];
static __device__ float         g_attn[(size_t)TT * HIDN];
static __device__ __nv_bfloat16 g_q2[(size_t)TT * HIDN];
static __device__ float         g_s2[TT];
static __device__ float         g_sum2[TT];
static __device__ float         g_cos[TT * 64];
static __device__ float         g_sin[TT * 64];

__device__ __forceinline__ uint32_t s2u(const void* p) { return (uint32_t)__cvta_generic_to_shared(p); }

// ---------------- RoPE table (fp64 inner) ----------------
__global__ void k_rope_tab(const int* __restrict__ pos) {
    int t = blockIdx.x, i = threadIdx.x;               // i: 0..63
    float ef = (float)(2 * i) / 128.0f;
    float invf = (float)(1.0 / pow(10000.0, (double)ef));
    float fr = (float)pos[t] * invf;                   // fp32 mul = reference rounding
    g_cos[t * 64 + i] = (float)cos((double)fr);
    g_sin[t * 64 + i] = (float)sin((double)fr);
}

// ---------------- activation prep ----------------
__global__ void k_prep_a(const int* __restrict__ qa) {
    int t = blockIdx.x, tid = threadIdx.x;
    const int* row = qa + (size_t)t * HIDN;
    __nv_bfloat16* arow = g_A + (size_t)t * HIDN;
    int s = 0;
    for (int c = tid; c < HIDN; c += 256) { int v = row[c]; s += v; arow[c] = __float2bfloat16((float)v); }
    __shared__ int red[256];
    red[tid] = s; __syncthreads();
    for (int k = 128; k > 0; k >>= 1) { if (tid < k) red[tid] += red[tid + k]; __syncthreads(); }
    if (tid == 0) g_asum[t] = (float)red[0];
}

__global__ void k_conv_w(const int* __restrict__ w, __nv_bfloat16* __restrict__ o, int n) {
    int i = blockIdx.x * blockDim.x + threadIdx.x;
    int stride = gridDim.x * blockDim.x;
    for (int v = i; v < n / 4; v += stride) {
        int4 x = ((const int4*)w)[v];
        __nv_bfloat162 p0 = {__float2bfloat16((float)x.x), __float2bfloat16((float)x.y)};
        __nv_bfloat162 p1 = {__float2bfloat16((float)x.z), __float2bfloat16((float)x.w)};
        ((__nv_bfloat162*)o)[2 * v] = p0;
        ((__nv_bfloat162*)o)[2 * v + 1] = p1;
    }
}

// ==================================================================
// bf16 HMMA GEMM v3 (measured-best 3-stage): CTA 256x128, warp 64x64,
// 3-stage cp.async pipeline, ldmatrix fragments, fused W4A8 epilogue.
// ==================================================================
#define GST 40
#define ASTG (256 * GST)
#define BSTG (128 * GST)
#define GEMM_SMEM (3 * (ASTG + BSTG) * 2)   // 92160 B

__device__ __forceinline__ void ldsm4(uint32_t& r0, uint32_t& r1, uint32_t& r2, uint32_t& r3, uint32_t a) {
    asm volatile("ldmatrix.sync.aligned.m8n8.x4.shared.b16 {%0,%1,%2,%3},[%4];\n"
                 : "=r"(r0), "=r"(r1), "=r"(r2), "=r"(r3) : "r"(a));
}
__device__ __forceinline__ void mmabf(float* c, const uint32_t* a, uint32_t b0, uint32_t b1) {
    asm volatile("mma.sync.aligned.m16n8k16.row.col.f32.bf16.bf16.f32 "
                 "{%0,%1,%2,%3},{%4,%5,%6,%7},{%8,%9},{%0,%1,%2,%3};\n"
                 : "+f"(c[0]), "+f"(c[1]), "+f"(c[2]), "+f"(c[3])
                 : "r"(a[0]), "r"(a[1]), "r"(a[2]), "r"(a[3]), "r"(b0), "r"(b1));
}
#define CP16(dst, src) asm volatile("cp.async.cg.shared.global [%0], [%1], 16;\n" :: "r"(dst), "l"(src))
#define CPCOMMIT()     asm volatile("cp.async.commit_group;\n")
#define CPWAIT1()      asm volatile("cp.async.wait_group 1;\n" ::: "memory")
#define CPWAIT0()      asm volatile("cp.async.wait_group 0;\n" ::: "memory")

__global__ __launch_bounds__(256, 1) void k_gemm(
    const __nv_bfloat16* __restrict__ A, const __nv_bfloat16* __restrict__ B,
    float* __restrict__ C, int M, int N, int K,
    const float* __restrict__ rs, const float* __restrict__ rsum,
    const float* __restrict__ cs, const float* __restrict__ cz)
{
    extern __shared__ __nv_bfloat16 gsm[];
    __nv_bfloat16* Ash = gsm;
    __nv_bfloat16* Bsh = gsm + 3 * ASTG;

    const int tid = threadIdx.x;
    const int warp = tid >> 5, lane = tid & 31;
    const int wm = warp >> 1, wn = warp & 1;
    const int g = lane >> 2, tq = lane & 3;
    const int sel = lane >> 3, l7 = lane & 7;
    const int bm0 = blockIdx.y * 256, bn0 = blockIdx.x * 128;

    const int r0 = tid >> 2, c0 = (tid & 3) * 8;
    const __nv_bfloat16* Abase = A + (size_t)(bm0 + r0) * K + c0;
    const __nv_bfloat16* Bbase = B + (size_t)(bn0 + r0) * K + c0;
    const size_t rowK64 = (size_t)64 * K;

    uint32_t sA = s2u(Ash), sB = s2u(Bsh);
    uint32_t dA = sA + (r0 * GST + c0) * 2;
    uint32_t dB = sB + (r0 * GST + c0) * 2;

    uint32_t aA = sA + ((wm * 64 + (sel & 1) * 8 + l7) * GST + (sel >> 1) * 8) * 2;
    uint32_t aB = sB + ((wn * 64 + (sel >> 1) * 8 + l7) * GST + (sel & 1) * 8) * 2;

    float acc[4][8][4];
#pragma unroll
    for (int i = 0; i < 4; i++)
#pragma unroll
        for (int j = 0; j < 8; j++) { acc[i][j][0]=0.f; acc[i][j][1]=0.f; acc[i][j][2]=0.f; acc[i][j][3]=0.f; }

    const int KT = K >> 5;

#pragma unroll
    for (int s = 0; s < 2; s++) {
        const __nv_bfloat16* Ak = Abase + s * 32;
        const __nv_bfloat16* Bk = Bbase + s * 32;
        uint32_t oA = dA + s * ASTG * 2, oB = dB + s * BSTG * 2;
#pragma unroll
        for (int q = 0; q < 4; q++) CP16(oA + q * 64 * GST * 2, Ak + q * rowK64);
#pragma unroll
        for (int q = 0; q < 2; q++) CP16(oB + q * 64 * GST * 2, Bk + q * rowK64);
        CPCOMMIT();
    }
    CPWAIT1();
    __syncthreads();

    for (int kb = 0; kb < KT; kb++) {
        const int st = kb % 3;
        if (kb + 2 < KT) {
            const int ns = (kb + 2) % 3;
            const __nv_bfloat16* Ak = Abase + (kb + 2) * 32;
            const __nv_bfloat16* Bk = Bbase + (kb + 2) * 32;
            uint32_t oA = dA + ns * ASTG * 2, oB = dB + ns * BSTG * 2;
#pragma unroll
            for (int q = 0; q < 4; q++) CP16(oA + q * 64 * GST * 2, Ak + q * rowK64);
#pragma unroll
            for (int q = 0; q < 2; q++) CP16(oB + q * 64 * GST * 2, Bk + q * rowK64);
            CPCOMMIT();
        }
        const uint32_t stA = aA + st * ASTG * 2;
        const uint32_t stB = aB + st * BSTG * 2;
#pragma unroll
        for (int ks = 0; ks < 2; ks++) {
            uint32_t af[4][4], bf[4][4];
#pragma unroll
            for (int mi = 0; mi < 4; mi++)
                ldsm4(af[mi][0], af[mi][1], af[mi][2], af[mi][3], stA + mi * 16 * GST * 2 + ks * 32);
#pragma unroll
            for (int p = 0; p < 4; p++)
                ldsm4(bf[p][0], bf[p][1], bf[p][2], bf[p][3], stB + p * 16 * GST * 2 + ks * 32);
#pragma unroll
            for (int mi = 0; mi < 4; mi++)
#pragma unroll
                for (int p = 0; p < 4; p++) {
                    mmabf(acc[mi][2 * p],     af[mi], bf[p][0], bf[p][1]);
                    mmabf(acc[mi][2 * p + 1], af[mi], bf[p][2], bf[p][3]);
                }
        }
        if (kb + 1 < KT) {
            CPWAIT1();
            __syncthreads();
        }
    }

#pragma unroll
    for (int mi = 0; mi < 4; mi++) {
        int rA = bm0 + wm * 64 + mi * 16 + g;
        int rB = rA + 8;
        float rsA = rs[rA], rmA = rsum[rA];
        float rsB = rs[rB], rmB = rsum[rB];
#pragma unroll
        for (int ni = 0; ni < 8; ni++) {
            int col = bn0 + wn * 64 + ni * 8 + 2 * tq;
            float cs0 = cs[col], cs1 = cs[col + 1];
            float cz0 = cz[col], cz1 = cz[col + 1];
            float2 o0, o1;
            o0.x = (rsA * cs0) * (acc[mi][ni][0] - cz0 * rmA);
            o0.y = (rsA * cs1) * (acc[mi][ni][1] - cz1 * rmA);
            o1.x = (rsB * cs0) * (acc[mi][ni][2] - cz0 * rmB);
            o1.y = (rsB * cs1) * (acc[mi][ni][3] - cz1 * rmB);
            *(float2*)&C[(size_t)rA * N + col] = o0;
            *(float2*)&C[(size_t)rB * N + col] = o1;
        }
    }
}

// ---------------- fused RoPE+split (Q,K) and split (V) ----------------
__device__ __forceinline__ void w_split(__half* hp, __half* lp, size_t off, float x) {
    __half h = __float2half_rn(x);
    hp[off] = h;
    lp[off] = __float2half_rn(x - __half2float(h));
}

__global__ __launch_bounds__(256) void k_split16() {
    int t = blockIdx.x, tid = threadIdx.x;
    const float* row = g_qkv + (size_t)t * QKVO;
    for (int v = tid; v < (NHQ + NKVH) * 64; v += 256) {
        int hh = v >> 6, i = v & 63;
        float c = g_cos[t * 64 + i], s = g_sin[t * 64 + i];
        const float* base = row + hh * HDIM;
        float x1 = base[i], x2 = base[64 + i];
        float r1 = x1 * c - x2 * s, r2 = x2 * c + x1 * s;
        if (hh < NHQ) {
            size_t o = ((size_t)hh * TT + t) * HDIM;
            w_split(g_qh, g_ql, o + i, r1);
            w_split(g_qh, g_ql, o + 64 + i, r2);
        } else {
            size_t o = ((size_t)(hh - NHQ) * TT + t) * HDIM;
            w_split(g_kh, g_kl, o + i, r1);
            w_split(g_kh, g_kl, o + 64 + i, r2);
        }
    }
    const float* vbase = row + (NHQ + NKVH) * HDIM;
    for (int v = tid; v < NKVH * HDIM; v += 256) {
        int kvh = v >> 7, d = v & 127;
        w_split(g_vh, g_vl, ((size_t)kvh * TT + t) * HDIM + d, vbase[kvh * HDIM + d]);
    }
}

// ======================================================================
// fp16 flash attention v5 (unchanged): BM=128/BN=64, pre-split fp16
// inputs, cp.async double-buffered K/V, Q frags hoisted to registers.
// ======================================================================
#define FS 136
#define QSZB (128 * FS * 2)
#define KSZB (64 * FS * 2)
#define STGB (4 * KSZB)
#define FLASH_SMEM5 (2 * QSZB + 2 * STGB)

__device__ __forceinline__ void ldsm4t(uint32_t& r0, uint32_t& r1, uint32_t& r2, uint32_t& r3, uint32_t a) {
    asm volatile("ldmatrix.sync.aligned.m8n8.x4.trans.shared.b16 {%0,%1,%2,%3},[%4];\n"
                 : "=r"(r0), "=r"(r1), "=r"(r2), "=r"(r3) : "r"(a));
}
__device__ __forceinline__ void mmaf16(float* c, const uint32_t* a, uint32_t b0, uint32_t b1) {
    asm volatile("mma.sync.aligned.m16n8k16.row.col.f32.f16.f16.f32 "
                 "{%0,%1,%2,%3},{%4,%5,%6,%7},{%8,%9},{%0,%1,%2,%3};\n"
                 : "+f"(c[0]), "+f"(c[1]), "+f"(c[2]), "+f"(c[3])
                 : "r"(a[0]), "r"(a[1]), "r"(a[2]), "r"(a[3]), "r"(b0), "r"(b1));
}
__device__ __forceinline__ uint32_t ph2(__half a, __half b) {
    return (uint32_t)__half_as_ushort(a) | ((uint32_t)__half_as_ushort(b) << 16);
}
__device__ __forceinline__ void splitp(float x, float y, uint32_t& hi, uint32_t& lo) {
    __half a = __float2half_rn(x), b = __float2half_rn(y);
    hi = ph2(a, b);
    lo = ph2(__float2half_rn(x - __half2float(a)), __float2half_rn(y - __half2float(b)));
}

__global__ __launch_bounds__(256) void k_flash5() {
    extern __shared__ char fsm[];
    const uint32_t SMB = s2u(fsm);

    const int tid = threadIdx.x;
    const int w = tid >> 5, lane = tid & 31;
    const int g = lane >> 2, tq = lane & 3;
    const int head = blockIdx.y, kvh = head >> 2;
    const int qb = (int)(gridDim.x - 1 - blockIdx.x);
    const int q0 = qb * 128;

    const int l7 = lane & 7, sel = lane >> 3;
    const uint32_t dQ = ((16 * w + (sel & 1) * 8 + l7) * FS + (sel >> 1) * 8) * 2;
    const uint32_t dK = (((sel >> 1) * 8 + l7) * FS + (sel & 1) * 8) * 2;
    const uint32_t dV = 2 * KSZB + (((sel & 1) * 8 + l7) * FS + (sel >> 1) * 8) * 2;

    for (int v = tid; v < 2048; v += 256) {
        int r = v >> 4, ch = v & 15;
        size_t so = ((size_t)head * TT + q0 + r) * HDIM + ch * 8;
        uint32_t dst = SMB + (r * FS + ch * 8) * 2;
        CP16(dst, g_qh + so);
        CP16(dst + QSZB, g_ql + so);
    }
    {
        uint32_t stg = SMB + 2 * QSZB;
        for (int v = tid; v < 1024; v += 256) {
            int r = v >> 4, ch = v & 15;
            size_t so = ((size_t)kvh * TT + r) * HDIM + ch * 8;
            uint32_t drow = stg + (r * FS + ch * 8) * 2;
            CP16(drow,            g_kh + so);
            CP16(drow + KSZB,     g_kl + so);
            CP16(drow + 2 * KSZB, g_vh + so);
            CP16(drow + 3 * KSZB, g_vl + so);
        }
    }
    CPCOMMIT();
    CPWAIT0();
    __syncthreads();

    uint32_t qfh[8][4], qfl[8][4];
#pragma unroll
    for (int kt = 0; kt < 8; kt++) {
        ldsm4(qfh[kt][0], qfh[kt][1], qfh[kt][2], qfh[kt][3], SMB + dQ + 32 * kt);
        ldsm4(qfl[kt][0], qfl[kt][1], qfl[kt][2], qfl[kt][3], SMB + QSZB + dQ + 32 * kt);
    }

    float m0r = -INFINITY, m1r = -INFINITY, l0r = 0.f, l1r = 0.f;
    float O[16][4];
#pragma unroll
    for (int t = 0; t < 16; t++) { O[t][0]=0.f; O[t][1]=0.f; O[t][2]=0.f; O[t][3]=0.f; }

    const int rowg = q0 + 16 * w + g;
    const int nkb = 2 * qb + 2;

    for (int kb = 0; kb < nkb; kb++) {
        if (kb > 0) { CPWAIT0(); __syncthreads(); }
        if (kb + 1 < nkb) {
            int k1 = (kb + 1) * 64;
            uint32_t stg = SMB + 2 * QSZB + ((kb + 1) & 1) * STGB;
            for (int v = tid; v < 1024; v += 256) {
                int r = v >> 4, ch = v & 15;
                size_t so = ((size_t)kvh * TT + k1 + r) * HDIM + ch * 8;
                uint32_t drow = stg + (r * FS + ch * 8) * 2;
                CP16(drow,            g_kh + so);
                CP16(drow + KSZB,     g_kl + so);
                CP16(drow + 2 * KSZB, g_vh + so);
                CP16(drow + 3 * KSZB, g_vl + so);
            }
            CPCOMMIT();
        }
        const uint32_t stg = SMB + 2 * QSZB + (kb & 1) * STGB;
        const uint32_t aKh = stg + dK, aKl = aKh + KSZB;
        const uint32_t aVh = stg + dV, aVl = aVh + KSZB;
        const int k0 = kb * 64;

        float sc[8][4];
#pragma unroll
        for (int j = 0; j < 8; j++) { sc[j][0]=0.f; sc[j][1]=0.f; sc[j][2]=0.f; sc[j][3]=0.f; }
#pragma unroll
        for (int kt = 0; kt < 8; kt++) {
            uint32_t kh[4], kl_[4];
#pragma unroll
            for (int p = 0; p < 4; p++) {
                ldsm4(kh[0], kh[1], kh[2], kh[3], aKh + 4352 * p + 32 * kt);
                ldsm4(kl_[0], kl_[1], kl_[2], kl_[3], aKl + 4352 * p + 32 * kt);
                mmaf16(sc[2 * p],     qfh[kt], kh[0], kh[1]);
                mmaf16(sc[2 * p],     qfh[kt], kl_[0], kl_[1]);
                mmaf16(sc[2 * p],     qfl[kt], kh[0], kh[1]);
                mmaf16(sc[2 * p + 1], qfh[kt], kh[2], kh[3]);
                mmaf16(sc[2 * p + 1], qfh[kt], kl_[2], kl_[3]);
                mmaf16(sc[2 * p + 1], qfl[kt], kh[2], kh[3]);
            }
        }

        bool tail = (kb >= 2 * qb);
#pragma unroll
        for (int j = 0; j < 8; j++) {
            int cb = k0 + 8 * j + 2 * tq;
#pragma unroll
            for (int e = 0; e < 2; e++) {
                float v0 = sc[j][e] * SCALE_QK;
                float v1 = sc[j][2 + e] * SCALE_QK;
                if (tail) {
                    if (cb + e > rowg)     v0 = -INFINITY;
                    if (cb + e > rowg + 8) v1 = -INFINITY;
                }
                sc[j][e] = v0; sc[j][2 + e] = v1;
            }
        }

        float mx0 = -INFINITY, mx1 = -INFINITY;
#pragma unroll
        for (int j = 0; j < 8; j++) {
            mx0 = fmaxf(mx0, fmaxf(sc[j][0], sc[j][1]));
            mx1 = fmaxf(mx1, fmaxf(sc[j][2], sc[j][3]));
        }
        mx0 = fmaxf(mx0, __shfl_xor_sync(0xffffffffu, mx0, 1));
        mx0 = fmaxf(mx0, __shfl_xor_sync(0xffffffffu, mx0, 2));
        mx1 = fmaxf(mx1, __shfl_xor_sync(0xffffffffu, mx1, 1));
        mx1 = fmaxf(mx1, __shfl_xor_sync(0xffffffffu, mx1, 2));
        float mn0 = fmaxf(m0r, mx0), mn1 = fmaxf(m1r, mx1);
        float c0 = __expf(m0r - mn0), c1 = __expf(m1r - mn1);
        m0r = mn0; m1r = mn1;
        float s0 = 0.f, s1 = 0.f;
#pragma unroll
        for (int j = 0; j < 8; j++) {
            sc[j][0] = __expf(sc[j][0] - mn0) * 1024.0f;
            sc[j][1] = __expf(sc[j][1] - mn0) * 1024.0f;
            sc[j][2] = __expf(sc[j][2] - mn1) * 1024.0f;
            sc[j][3] = __expf(sc[j][3] - mn1) * 1024.0f;
            s0 += sc[j][0] + sc[j][1];
            s1 += sc[j][2] + sc[j][3];
        }
        s0 += __shfl_xor_sync(0xffffffffu, s0, 1);
        s0 += __shfl_xor_sync(0xffffffffu, s0, 2);
        s1 += __shfl_xor_sync(0xffffffffu, s1, 1);
        s1 += __shfl_xor_sync(0xffffffffu, s1, 2);
        l0r = l0r * c0 + s0;
        l1r = l1r * c1 + s1;
#pragma unroll
        for (int t = 0; t < 16; t++) { O[t][0] *= c0; O[t][1] *= c0; O[t][2] *= c1; O[t][3] *= c1; }

#pragma unroll
        for (int jj = 0; jj < 4; jj++) {
            uint32_t pa[4], pl[4];
            splitp(sc[2 * jj][0],     sc[2 * jj][1],     pa[0], pl[0]);
            splitp(sc[2 * jj][2],     sc[2 * jj][3],     pa[1], pl[1]);
            splitp(sc[2 * jj + 1][0], sc[2 * jj + 1][1], pa[2], pl[2]);
            splitp(sc[2 * jj + 1][2], sc[2 * jj + 1][3], pa[3], pl[3]);
#pragma unroll
            for (int q = 0; q < 8; q++) {
                uint32_t vh[4], vl_[4];
                ldsm4t(vh[0], vh[1], vh[2], vh[3], aVh + 4352 * jj + 32 * q);
                ldsm4t(vl_[0], vl_[1], vl_[2], vl_[3], aVl + 4352 * jj + 32 * q);
                mmaf16(O[2 * q],     pa, vh[0], vh[1]);
                mmaf16(O[2 * q],     pa, vl_[0], vl_[1]);
                mmaf16(O[2 * q],     pl, vh[0], vh[1]);
                mmaf16(O[2 * q + 1], pa, vh[2], vh[3]);
                mmaf16(O[2 * q + 1], pa, vl_[2], vl_[3]);
                mmaf16(O[2 * q + 1], pl, vh[2], vh[3]);
            }
        }
    }

#pragma unroll
    for (int t = 0; t < 16; t++) {
        int col = head * HDIM + 8 * t + 2 * tq;
        float2 u;
        u.x = O[t][0] / l0r;  u.y = O[t][1] / l0r;
        *(float2*)&g_attn[(size_t)rowg * HIDN + col] = u;
        u.x = O[t][2] / l1r;  u.y = O[t][3] / l1r;
        *(float2*)&g_attn[(size_t)(rowg + 8) * HIDN + col] = u;
    }
}

// ---------------- dynamic quant with sum (reciprocal hoisted) ----------------
__global__ __launch_bounds__(256) void k_quant() {
    __shared__ float xrow[HIDN];
    __shared__ float red[256];
    int t = blockIdx.x, tid = threadIdx.x;
    const float* src = g_attn + (size_t)t * HIDN;
    float amax = 0.f;
    for (int c = tid; c < HIDN; c += 256) { float x = src[c]; xrow[c] = x; amax = fmaxf(amax, fabsf(x)); }
    red[tid] = amax; __syncthreads();
    for (int k = 128; k > 0; k >>= 1) { if (tid < k) red[tid] = fmaxf(red[tid], red[tid + k]); __syncthreads(); }
    float s = fmaxf(red[0], 1e-8f) / 127.0f;
    float sinv = 1.0f / s;
    __nv_bfloat16* q = g_q2 + (size_t)t * HIDN;
    float qs = 0.f;
    for (int c = tid; c < HIDN; c += 256) {
        float v = rintf(xrow[c] * sinv);
        v = fminf(fmaxf(v, -127.f), 127.f);
        q[c] = __float2bfloat16(v);
        qs += v;
    }
    __syncthreads();
    red[tid] = qs; __syncthreads();
    for (int k = 128; k > 0; k >>= 1) { if (tid < k) red[tid] += red[tid + k]; __syncthreads(); }
    if (tid == 0) { g_s2[t] = s; g_sum2[t] = red[0]; }
}

// ---------------- launch ----------------
extern "C" void kernel_launch(void* const* d_in, const int* in_sizes, int n_in,
                              void* d_out, int out_size) {
    const int*   positions   = (const int*)d_in[0];
    const int*   q_act       = (const int*)d_in[1];
    const float* act_scale   = (const float*)d_in[2];
    const int*   w_qkv_q     = (const int*)d_in[3];
    const float* w_qkv_scale = (const float*)d_in[4];
    const float* w_qkv_zero  = (const float*)d_in[5];
    const int*   w_o_q       = (const int*)d_in[6];
    const float* w_o_scale   = (const float*)d_in[7];
    const float* w_o_zero    = (const float*)d_in[8];
    float* out = (float*)d_out;

    __nv_bfloat16 *A, *Wqkv, *Wo, *q2;
    float *asum, *qkv, *s2, *sum2;
    cudaGetSymbolAddress((void**)&A,    g_A);
    cudaGetSymbolAddress((void**)&Wqkv, g_Wqkv);
    cudaGetSymbolAddress((void**)&Wo,   g_Wo);
    cudaGetSymbolAddress((void**)&q2,   g_q2);
    cudaGetSymbolAddress((void**)&asum, g_asum);
    cudaGetSymbolAddress((void**)&qkv,  g_qkv);
    cudaGetSymbolAddress((void**)&s2,   g_s2);
    cudaGetSymbolAddress((void**)&sum2, g_sum2);

    cudaFuncSetAttribute(k_flash5, cudaFuncAttributeMaxDynamicSharedMemorySize, FLASH_SMEM5);
    cudaFuncSetAttribute(k_gemm,   cudaFuncAttributeMaxDynamicSharedMemorySize, GEMM_SMEM);

    k_rope_tab<<<TT, 64>>>(positions);
    k_prep_a<<<TT, 256>>>(q_act);
    k_conv_w<<<2048, 256>>>(w_qkv_q, Wqkv, QKVO * HIDN);

    dim3 g1(QKVO / 128, TT / 256);
    k_gemm<<<g1, 256, GEMM_SMEM>>>(A, Wqkv, qkv, TT, QKVO, HIDN, act_scale, asum, w_qkv_scale, w_qkv_zero);

    k_split16<<<TT, 256>>>();

    dim3 g3(TT / 128, NHQ);
    k_flash5<<<g3, 256, FLASH_SMEM5>>>();

    k_quant<<<TT, 256>>>();

    k_conv_w<<<2048, 256>>>(w_o_q, Wo, HIDN * HIDN);

    dim3 g4(HIDN / 128, TT / 256);
    k_gemm<<<g4, 256, GEMM_SMEM>>>(q2, Wo, out, TT, HIDN, HIDN, s2, sum2, w_o_scale, w_o_zero);
}